// round 2
// baseline (speedup 1.0000x reference)
#include <cuda_runtime.h>
#include <cstdint>
#include <cstddef>

// ---------------------------------------------------------------------------
// CBFNet on GB300: compact dead edges -> fused-gather SGEMM (f32x2) edge MLP
// -> gated segment softmax (folded normalization, vector RED) -> agent MLP.
// ---------------------------------------------------------------------------

#define MAXE 800000
#define MAXN 50000

typedef unsigned long long ull;

// Scratch (allocation-free rule: __device__ globals)
__device__ float    g_H[(size_t)MAXE * 256];
__device__ float    g_MSG[(size_t)MAXE * 128];
__device__ float    g_logits[MAXE];
__device__ int      g_eidx[MAXE];
__device__ int      g_rcvc[MAXE];
__device__ unsigned g_segmax[MAXN];
__device__ float    g_denom[MAXN];
__device__ float    g_aggr[(size_t)MAXN * 128];
__device__ float    g_X0[(size_t)MAXN * 128];
__device__ float    g_X1[(size_t)MAXN * 256];
__device__ float    g_X2[(size_t)MAXN * 256];
__device__ int      g_count[1];

// ---- f32x2 helpers (Blackwell paired FP32 pipe) ----
__device__ __forceinline__ ull pk2(float a) {
    ull r; unsigned u = __float_as_uint(a);
    asm("mov.b64 %0, {%1, %2};" : "=l"(r) : "r"(u), "r"(u));
    return r;
}
__device__ __forceinline__ ull pkp(float x, float y) {
    ull r;
    asm("mov.b64 %0, {%1, %2};" : "=l"(r)
        : "r"(__float_as_uint(x)), "r"(__float_as_uint(y)));
    return r;
}
__device__ __forceinline__ void fma2(ull& d, ull a, ull b) {
    asm("fma.rn.f32x2 %0, %1, %2, %0;" : "+l"(d) : "l"(a), "l"(b));
}
__device__ __forceinline__ float2 upk(ull v) {
    float2 r;
    asm("mov.b64 {%0, %1}, %2;" : "=f"(r.x), "=f"(r.y) : "l"(v));
    return r;
}

// ---- monotone float<->uint mapping for atomicMax on floats ----
__device__ __forceinline__ unsigned fmap(float f) {
    unsigned u = __float_as_uint(f);
    return (u & 0x80000000u) ? ~u : (u | 0x80000000u);
}
__device__ __forceinline__ float funmap(unsigned u) {
    return __uint_as_float((u & 0x80000000u) ? (u ^ 0x80000000u) : ~u);
}

// ---------------------------------------------------------------------------
// Tiled SGEMM: C[M,NT] = act(A[M,KD] @ B[KD,NT] + bias), M read from device.
// GATHER mode builds A rows on the fly from node/edge features via g_eidx.
// BM=BN=128, BK=16, 256 threads, 8x8 microtile, f32x2 accumulators (pairs
// along N), double-buffered smem with register-staged prefetch.
// ---------------------------------------------------------------------------
#define BM 128
#define BN 128
#define BK 16

template<int KD, int NT, bool GATHER, bool RELU>
__global__ __launch_bounds__(256, 2)
void gemm_k(const float* __restrict__ A,
            const float* __restrict__ nodef,
            const float* __restrict__ edgef,
            const int*   __restrict__ senders,
            const int*   __restrict__ receivers,
            const float* __restrict__ B,
            const float* __restrict__ bias,
            float*       __restrict__ C,
            const int*   __restrict__ mptr)
{
    const int M = *mptr;
    const int row0 = blockIdx.x * BM;
    if (row0 >= M) return;
    const int n0  = blockIdx.y * BN;
    const int tid = threadIdx.x;

    __shared__ float As[2][BK][BM];
    __shared__ float Bs[2][BK][BN];
    __shared__ int sS[BM], sR[BM], sE[BM];

    if (GATHER) {
        if (tid < BM) {
            int m = row0 + tid;
            int e = g_eidx[(m < M) ? m : 0];
            sE[tid] = e;
            sS[tid] = senders[e];
            sR[tid] = receivers[e];
        }
        __syncthreads();
    }

    // A-load mapping: thread -> row a_m, k-offsets a_k0 + {0,4}
    const int a_m  = tid >> 1;
    const int a_k0 = (tid & 1) * 8;
    // B-load mapping: thread -> k b_k, col offsets b_n + {0,4}
    const int b_k  = tid >> 4;
    const int b_n  = (tid & 15) * 8;

    float4 ra[2], rb[2];

    auto loadA = [&](int kb) {
        #pragma unroll
        for (int i = 0; i < 2; ++i) {
            int k   = kb * BK + a_k0 + i * 4;
            int row = row0 + a_m;
            float4 v = make_float4(0.f, 0.f, 0.f, 0.f);
            if (row < M) {
                if (GATHER) {
                    if (k < 64)       v = *(const float4*)(nodef + (size_t)sS[a_m] * 64 + k);
                    else if (k < 128) v = *(const float4*)(nodef + (size_t)sR[a_m] * 64 + (k - 64));
                    else              v = *(const float4*)(edgef + (size_t)sE[a_m] * 32 + (k - 128));
                } else {
                    v = *(const float4*)(A + (size_t)row * KD + k);
                }
            }
            ra[i] = v;
        }
    };
    auto loadB = [&](int kb) {
        #pragma unroll
        for (int i = 0; i < 2; ++i) {
            int k = kb * BK + b_k;
            rb[i] = *(const float4*)(B + (size_t)k * NT + n0 + b_n + i * 4);
        }
    };
    auto stash = [&](int b) {
        #pragma unroll
        for (int i = 0; i < 2; ++i) {
            int kl = a_k0 + i * 4;
            As[b][kl    ][a_m] = ra[i].x;
            As[b][kl + 1][a_m] = ra[i].y;
            As[b][kl + 2][a_m] = ra[i].z;
            As[b][kl + 3][a_m] = ra[i].w;
            *(float4*)&Bs[b][b_k][b_n + i * 4] = rb[i];
        }
    };

    loadA(0); loadB(0);
    stash(0);
    __syncthreads();

    ull acc[8][4] = {};
    const int my = (tid >> 4) * 8;
    const int nx = (tid & 15) * 8;
    constexpr int NKB = KD / BK;
    int buf = 0;

    #pragma unroll 1
    for (int kb = 0; kb < NKB; ++kb) {
        if (kb + 1 < NKB) { loadA(kb + 1); loadB(kb + 1); }
        #pragma unroll
        for (int k = 0; k < BK; ++k) {
            float4 A0 = *(const float4*)&As[buf][k][my];
            float4 A1 = *(const float4*)&As[buf][k][my + 4];
            float4 B0 = *(const float4*)&Bs[buf][k][nx];
            float4 B1 = *(const float4*)&Bs[buf][k][nx + 4];
            ull bb0 = pkp(B0.x, B0.y), bb1 = pkp(B0.z, B0.w);
            ull bb2 = pkp(B1.x, B1.y), bb3 = pkp(B1.z, B1.w);
            float av[8] = {A0.x, A0.y, A0.z, A0.w, A1.x, A1.y, A1.z, A1.w};
            #pragma unroll
            for (int r = 0; r < 8; ++r) {
                ull ar = pk2(av[r]);
                fma2(acc[r][0], ar, bb0);
                fma2(acc[r][1], ar, bb1);
                fma2(acc[r][2], ar, bb2);
                fma2(acc[r][3], ar, bb3);
            }
        }
        if (kb + 1 < NKB) {
            stash(buf ^ 1);
            __syncthreads();
            buf ^= 1;
        }
    }

    float bv[8];
    #pragma unroll
    for (int j = 0; j < 8; ++j) bv[j] = bias[n0 + nx + j];

    #pragma unroll
    for (int r = 0; r < 8; ++r) {
        int row = row0 + my + r;
        if (row < M) {
            float o[8];
            #pragma unroll
            for (int c = 0; c < 4; ++c) {
                float2 v = upk(acc[r][c]);
                o[2 * c]     = v.x + bv[2 * c];
                o[2 * c + 1] = v.y + bv[2 * c + 1];
            }
            if (RELU) {
                #pragma unroll
                for (int j = 0; j < 8; ++j) o[j] = fmaxf(o[j], 0.f);
            }
            float* cp = C + (size_t)row * NT + n0 + nx;
            *(float4*)cp       = make_float4(o[0], o[1], o[2], o[3]);
            *(float4*)(cp + 4) = make_float4(o[4], o[5], o[6], o[7]);
        }
    }
}

// ---------------------------------------------------------------------------
// Small kernels
// ---------------------------------------------------------------------------
__global__ void init_k(int n_nodes) {
    int i = blockIdx.x * blockDim.x + threadIdx.x;
    if (i < n_nodes * 128) g_aggr[i] = 0.f;
    if (i < n_nodes) { g_denom[i] = 0.f; g_segmax[i] = 0u; }
    if (i == 0) g_count[0] = 0;
}

// Keep only edges whose receiver < n_agents (others can't affect the output).
__global__ void compact_k(const int* __restrict__ receivers,
                          const int* __restrict__ nag, int n_edges) {
    int e = blockIdx.x * blockDim.x + threadIdx.x;
    if (e >= n_edges) return;
    int r = receivers[e];
    if (r < *nag) {
        int p = atomicAdd(g_count, 1);
        g_eidx[p] = e;
        g_rcvc[p] = r;
    }
}

// logit = msg . w_gate + b_gate ; atomicMax into per-receiver max.
__global__ void logits_k(const float* __restrict__ w_gate,
                         const float* __restrict__ b_gate) {
    int idx  = blockIdx.x * blockDim.x + threadIdx.x;
    int row  = idx >> 5, lane = idx & 31;
    if (row >= g_count[0]) return;
    float4 m4 = *(const float4*)(g_MSG + (size_t)row * 128 + lane * 4);
    float4 g4 = *(const float4*)(w_gate + lane * 4);
    float s = m4.x * g4.x + m4.y * g4.y + m4.z * g4.z + m4.w * g4.w;
    #pragma unroll
    for (int o = 16; o; o >>= 1) s += __shfl_xor_sync(0xffffffffu, s, o);
    if (lane == 0) {
        float lg = s + b_gate[0];
        g_logits[row] = lg;
        atomicMax(&g_segmax[g_rcvc[row]], fmap(lg));
    }
}

// w = exp(logit - segmax); denom += w; aggr += w * msg (vector RED).
// Normalization by denom is folded into norm_k (softmax algebra).
__global__ void aggr_k() {
    int idx = blockIdx.x * blockDim.x + threadIdx.x;
    int row = idx >> 5, lane = idx & 31;
    if (row >= g_count[0]) return;
    int rv = g_rcvc[row];
    float w = expf(g_logits[row] - funmap(g_segmax[rv]));
    if (lane == 0) atomicAdd(&g_denom[rv], w);
    float4 m4 = *(const float4*)(g_MSG + (size_t)row * 128 + lane * 4);
    float* dst = g_aggr + (size_t)rv * 128 + lane * 4;
    asm volatile("red.global.add.v4.f32 [%0], {%1, %2, %3, %4};"
                 :: "l"(dst), "f"(m4.x * w), "f"(m4.y * w),
                    "f"(m4.z * w), "f"(m4.w * w)
                 : "memory");
}

__global__ void norm_k(const int* __restrict__ nag, int n_nodes) {
    int i = blockIdx.x * blockDim.x + threadIdx.x;
    if (i >= n_nodes * 128) return;
    int row = i >> 7;
    if (row < *nag) g_X0[i] = g_aggr[i] / (g_denom[row] + 1e-9f);
}

__global__ void out_k(const float* __restrict__ W, const float* __restrict__ b,
                      const int* __restrict__ nag, float* __restrict__ out) {
    int idx = blockIdx.x * blockDim.x + threadIdx.x;
    int row = idx >> 5, lane = idx & 31;
    if (row >= *nag) return;
    const float4* xr = (const float4*)(g_X2 + (size_t)row * 256);
    const float4* wr = (const float4*)W;
    float s = 0.f;
    #pragma unroll
    for (int j = 0; j < 2; ++j) {
        float4 x = xr[lane + 32 * j], wv = wr[lane + 32 * j];
        s += x.x * wv.x + x.y * wv.y + x.z * wv.z + x.w * wv.w;
    }
    #pragma unroll
    for (int o = 16; o; o >>= 1) s += __shfl_xor_sync(0xffffffffu, s, o);
    if (lane == 0) out[row] = tanhf(s + b[0]);
}

// ---------------------------------------------------------------------------
extern "C" void kernel_launch(void* const* d_in, const int* in_sizes, int n_in,
                              void* d_out, int out_size)
{
    const float* node_feats = (const float*)d_in[0];
    const float* edge_feats = (const float*)d_in[1];
    const float* W_msg1 = (const float*)d_in[2];
    const float* b_msg1 = (const float*)d_in[3];
    const float* W_msg2 = (const float*)d_in[4];
    const float* b_msg2 = (const float*)d_in[5];
    const float* w_gate = (const float*)d_in[6];
    const float* b_gate = (const float*)d_in[7];
    const float* W_h1   = (const float*)d_in[8];
    const float* b_h1   = (const float*)d_in[9];
    const float* W_h2   = (const float*)d_in[10];
    const float* b_h2   = (const float*)d_in[11];
    const float* W_out  = (const float*)d_in[12];
    const float* b_out  = (const float*)d_in[13];
    const int*   senders   = (const int*)d_in[14];
    const int*   receivers = (const int*)d_in[15];
    const int*   nag       = (const int*)d_in[16];
    float* out = (float*)d_out;

    int n_nodes = in_sizes[0] / 64;
    int n_edges = in_sizes[14];

    float *pH, *pMSG, *pX0, *pX1, *pX2;
    int *pcount;
    cudaGetSymbolAddress((void**)&pH,     g_H);
    cudaGetSymbolAddress((void**)&pMSG,   g_MSG);
    cudaGetSymbolAddress((void**)&pX0,    g_X0);
    cudaGetSymbolAddress((void**)&pX1,    g_X1);
    cudaGetSymbolAddress((void**)&pX2,    g_X2);
    cudaGetSymbolAddress((void**)&pcount, g_count);

    const int t = 256;
    init_k<<<(n_nodes * 128 + t - 1) / t, t>>>(n_nodes);
    compact_k<<<(n_edges + t - 1) / t, t>>>(receivers, nag, n_edges);

    // Edge MLP (compacted rows): [cnt,160]@[160,256] relu ; [cnt,256]@[256,128] relu
    dim3 g1((n_edges + BM - 1) / BM, 2);
    gemm_k<160, 256, true,  true><<<g1, 256>>>(nullptr, node_feats, edge_feats,
                                               senders, receivers,
                                               W_msg1, b_msg1, pH, pcount);
    dim3 g2((n_edges + BM - 1) / BM, 1);
    gemm_k<256, 128, false, true><<<g2, 256>>>(pH, nullptr, nullptr, nullptr, nullptr,
                                               W_msg2, b_msg2, pMSG, pcount);

    // Gated segment softmax aggregation
    logits_k<<<(n_edges * 32 + t - 1) / t, t>>>(w_gate, b_gate);
    aggr_k<<<(n_edges * 32 + t - 1) / t, t>>>();
    norm_k<<<(n_nodes * 128 + t - 1) / t, t>>>(nag, n_nodes);

    // Agent MLP: [na,128]@[128,256] relu ; [na,256]@[256,256] relu ; dot+tanh
    dim3 g3((n_nodes + BM - 1) / BM, 2);
    gemm_k<128, 256, false, true><<<g3, 256>>>(pX0, nullptr, nullptr, nullptr, nullptr,
                                               W_h1, b_h1, pX1, nag);
    gemm_k<256, 256, false, true><<<g3, 256>>>(pX1, nullptr, nullptr, nullptr, nullptr,
                                               W_h2, b_h2, pX2, nag);
    out_k<<<(n_nodes * 32 + t - 1) / t, t>>>(W_out, b_out, nag, out);
}

// round 8
// speedup vs baseline: 1.2530x; 1.2530x over previous
#include <cuda_runtime.h>
#include <cuda_bf16.h>
#include <cstdint>
#include <cstddef>

// ---------------------------------------------------------------------------
// CBFNet on GB300 (compute_103 — no tcgen05, no cp.async):
//   compact dead edges (warp-aggregated) -> gather+split convert ->
//   bf16 3-term-split HMMA edge MLP (register-staged smem double buffer) ->
//   gated segment softmax (folded norm, vector RED) -> agent MLP (f32x2).
// ---------------------------------------------------------------------------

#define MAXE 800000
#define MAXN 50000

typedef unsigned long long ull;

// Scratch (allocation-free rule: __device__ globals)
__device__ uint32_t g_Ahi[(size_t)MAXE * 80];    // gathered A, bf16x2 hi plane [m][160]
__device__ uint32_t g_Alo[(size_t)MAXE * 80];    // lo plane
__device__ uint32_t g_Hhi[(size_t)MAXE * 128];   // H bf16x2 hi plane [m][256]
__device__ uint32_t g_Hlo[(size_t)MAXE * 128];   // lo plane
__device__ float    g_MSG[(size_t)MAXE * 128];
__device__ float    g_logits[MAXE];
__device__ int      g_eidx[MAXE];
__device__ int      g_rcvc[MAXE];
__device__ unsigned g_segmax[MAXN];
__device__ float    g_denom[MAXN];
__device__ float    g_aggr[(size_t)MAXN * 128];
__device__ float    g_X0[(size_t)MAXN * 128];
__device__ float    g_X1[(size_t)MAXN * 256];
__device__ float    g_X2[(size_t)MAXN * 256];
__device__ int      g_count[1];

// Transposed bf16 weight planes [N][K] (row.col mma layout: B^T rows k-contig)
__device__ __nv_bfloat16 g_W1Thi[256 * 160];
__device__ __nv_bfloat16 g_W1Tlo[256 * 160];
__device__ __nv_bfloat16 g_W2Thi[128 * 256];
__device__ __nv_bfloat16 g_W2Tlo[128 * 256];

// ============================ helpers ======================================
// fp32 pair -> packed bf16x2 hi/lo planes
__device__ __forceinline__ void split2(float a, float b, uint32_t& hp, uint32_t& lp) {
    __nv_bfloat16 ha = __float2bfloat16(a), hb = __float2bfloat16(b);
    __nv_bfloat16 la = __float2bfloat16(a - __bfloat162float(ha));
    __nv_bfloat16 lb = __float2bfloat16(b - __bfloat162float(hb));
    hp = ((uint32_t)__bfloat16_as_ushort(hb) << 16) | __bfloat16_as_ushort(ha);
    lp = ((uint32_t)__bfloat16_as_ushort(lb) << 16) | __bfloat16_as_ushort(la);
}

__device__ __forceinline__ void mma16816(float* c, const uint32_t* a, const uint32_t* b) {
    asm volatile(
        "mma.sync.aligned.m16n8k16.row.col.f32.bf16.bf16.f32 "
        "{%0,%1,%2,%3}, {%4,%5,%6,%7}, {%8,%9}, {%0,%1,%2,%3};"
        : "+f"(c[0]), "+f"(c[1]), "+f"(c[2]), "+f"(c[3])
        : "r"(a[0]), "r"(a[1]), "r"(a[2]), "r"(a[3]), "r"(b[0]), "r"(b[1]));
}

// ======================= prep kernels ======================================
// Transpose + split weights: W [K][N] fp32 -> Thi/Tlo [N][K] bf16
__global__ void prepW_k(const float* __restrict__ W,
                        __nv_bfloat16* __restrict__ Thi,
                        __nv_bfloat16* __restrict__ Tlo, int K, int N) {
    int i = blockIdx.x * blockDim.x + threadIdx.x;
    if (i >= K * N) return;
    int n = i / K, k = i % K;
    float v = W[k * N + n];
    __nv_bfloat16 h = __float2bfloat16(v);
    Thi[n * K + k] = h;
    Tlo[n * K + k] = __float2bfloat16(v - __bfloat162float(h));
}

// Gather [sender||receiver||edge] fp32 rows -> packed bf16 hi/lo planes [m][160]
__global__ void convertA_k(const float* __restrict__ nodef,
                           const float* __restrict__ edgef,
                           const int*   __restrict__ senders,
                           const int*   __restrict__ receivers, int n_edges) {
    int i = blockIdx.x * blockDim.x + threadIdx.x;
    int row = i / 40, q = i % 40;
    if (row >= g_count[0]) return;
    int e = g_eidx[row];
    int pos = q * 4;
    const float* src;
    if (pos < 64)       src = nodef + (size_t)senders[e] * 64 + pos;
    else if (pos < 128) src = nodef + (size_t)receivers[e] * 64 + (pos - 64);
    else                src = edgef + (size_t)e * 32 + (pos - 128);
    float4 f = *(const float4*)src;
    uint32_t h0, l0, h1, l1;
    split2(f.x, f.y, h0, l0);
    split2(f.z, f.w, h1, l1);
    size_t o = (size_t)row * 80 + q * 2;
    g_Ahi[o] = h0; g_Ahi[o + 1] = h1;
    g_Alo[o] = l0; g_Alo[o + 1] = l1;
}

// ======================= HMMA 3-term-split GEMM ============================
// C[M, NT] = relu(A @ B + bias); A bf16 hi/lo planes [M][KD] row-major,
// B bf16 hi/lo planes [NT][KD] (transposed). CTA 128x128, 8 warps 4(M)x2(N),
// warp tile 32x64, BK=32. Register-staged double-buffered smem (plain
// ld.global/st.shared — NO cp.async), +8 pad for conflict-free frag loads.
// 3 mma passes: hi*hi + hi*lo + lo*hi (fp32 accum).
#define APAD 40   // 32 + 8 pad (bf16 elems per smem row)

template<int KD, int NT, bool SPLIT>
__global__ __launch_bounds__(256, 1)
void mma_gemm(const __nv_bfloat16* __restrict__ Ahi,
              const __nv_bfloat16* __restrict__ Alo,
              const __nv_bfloat16* __restrict__ Bhi,
              const __nv_bfloat16* __restrict__ Blo,
              const float*    __restrict__ bias,
              uint32_t*       __restrict__ Chi,
              uint32_t*       __restrict__ Clo,
              float*          __restrict__ Cf,
              const int*      __restrict__ mptr)
{
    const int M = *mptr;
    const int row0 = blockIdx.x * 128;
    if (row0 >= M) return;
    const int n0  = blockIdx.y * 128;
    const int tid  = threadIdx.x;
    const int lane = tid & 31, wid = tid >> 5;
    const int gq = lane >> 2, tq = lane & 3;
    const int wr = (wid & 3) * 32;      // warp row base (M)
    const int wc = (wid >> 2) * 64;     // warp col base (N)

    extern __shared__ char dsm[];
    __nv_bfloat16* S = (__nv_bfloat16*)dsm;
    // layout (bf16 elements): A planes [buf*2+p][128][APAD] at 0, B at BOFF
    const int BOFF = 2 * 2 * 128 * APAD;   // 20480 elements

    // Fill mapping: thread covers 2 chunks per plane; chunk s = tid*2+i:
    // row = s>>2 (0..127), ks = (s&3)*8 (0,8,16,24)
    const int f_row0 = (tid * 2)     >> 2, f_ks0 = ((tid * 2)     & 3) * 8;
    const int f_row1 = (tid * 2 + 1) >> 2, f_ks1 = ((tid * 2 + 1) & 3) * 8;

    uint4 stA[2][2], stB[2][2];   // [plane][i] staged 16B chunks

    auto gload = [&](int kb) {
        #pragma unroll
        for (int p = 0; p < 2; ++p) {
            const __nv_bfloat16* A_ = p ? Alo : Ahi;
            const __nv_bfloat16* B_ = p ? Blo : Bhi;
            stA[p][0] = *(const uint4*)(A_ + (size_t)(row0 + f_row0) * KD + kb * 32 + f_ks0);
            stA[p][1] = *(const uint4*)(A_ + (size_t)(row0 + f_row1) * KD + kb * 32 + f_ks1);
            stB[p][0] = *(const uint4*)(B_ + (size_t)(n0  + f_row0) * KD + kb * 32 + f_ks0);
            stB[p][1] = *(const uint4*)(B_ + (size_t)(n0  + f_row1) * KD + kb * 32 + f_ks1);
        }
    };
    auto sstore = [&](int b) {
        #pragma unroll
        for (int p = 0; p < 2; ++p) {
            *(uint4*)(S + ((b * 2 + p) * 128 + f_row0) * APAD + f_ks0) = stA[p][0];
            *(uint4*)(S + ((b * 2 + p) * 128 + f_row1) * APAD + f_ks1) = stA[p][1];
            *(uint4*)(S + BOFF + ((b * 2 + p) * 128 + f_row0) * APAD + f_ks0) = stB[p][0];
            *(uint4*)(S + BOFF + ((b * 2 + p) * 128 + f_row1) * APAD + f_ks1) = stB[p][1];
        }
    };

    float acc[2][8][4];
    #pragma unroll
    for (int mi = 0; mi < 2; ++mi)
        #pragma unroll
        for (int j = 0; j < 8; ++j)
            #pragma unroll
            for (int q = 0; q < 4; ++q) acc[mi][j][q] = 0.f;

    constexpr int NKB = KD / 32;
    int buf = 0;

    gload(0);
    sstore(0);
    __syncthreads();

    #pragma unroll 1
    for (int kb = 0; kb < NKB; ++kb) {
        if (kb + 1 < NKB) gload(kb + 1);

        #pragma unroll
        for (int kk = 0; kk < 32; kk += 16) {
            uint32_t af[2][2][4];
            #pragma unroll
            for (int p = 0; p < 2; ++p) {
                const __nv_bfloat16* base = S + (buf * 2 + p) * 128 * APAD;
                #pragma unroll
                for (int mi = 0; mi < 2; ++mi) {
                    int r = wr + mi * 16 + gq;
                    int k = kk + tq * 2;
                    af[p][mi][0] = *(const uint32_t*)(base + (r)     * APAD + k);
                    af[p][mi][1] = *(const uint32_t*)(base + (r + 8) * APAD + k);
                    af[p][mi][2] = *(const uint32_t*)(base + (r)     * APAD + k + 8);
                    af[p][mi][3] = *(const uint32_t*)(base + (r + 8) * APAD + k + 8);
                }
            }
            const __nv_bfloat16* bh = S + BOFF + (buf * 2)     * 128 * APAD;
            const __nv_bfloat16* bl = S + BOFF + (buf * 2 + 1) * 128 * APAD;
            #pragma unroll
            for (int j = 0; j < 8; ++j) {
                int n = wc + j * 8 + gq;
                int k = kk + tq * 2;
                uint32_t bh0[2], bl0[2];
                bh0[0] = *(const uint32_t*)(bh + n * APAD + k);
                bh0[1] = *(const uint32_t*)(bh + n * APAD + k + 8);
                bl0[0] = *(const uint32_t*)(bl + n * APAD + k);
                bl0[1] = *(const uint32_t*)(bl + n * APAD + k + 8);
                #pragma unroll
                for (int mi = 0; mi < 2; ++mi) {
                    mma16816(acc[mi][j], af[0][mi], bh0);  // hi*hi
                    mma16816(acc[mi][j], af[0][mi], bl0);  // hi*lo
                    mma16816(acc[mi][j], af[1][mi], bh0);  // lo*hi
                }
            }
        }

        if (kb + 1 < NKB) {
            sstore(buf ^ 1);
            __syncthreads();
            buf ^= 1;
        }
    }

    // Epilogue: bias + relu; SPLIT -> bf16 hi/lo planes, else fp32
    #pragma unroll
    for (int mi = 0; mi < 2; ++mi) {
        int r1 = row0 + wr + mi * 16 + gq;
        int r2 = r1 + 8;
        #pragma unroll
        for (int j = 0; j < 8; ++j) {
            int gcol = n0 + wc + j * 8 + tq * 2;
            float2 bv = *(const float2*)(bias + gcol);
            float v0 = fmaxf(acc[mi][j][0] + bv.x, 0.f);
            float v1 = fmaxf(acc[mi][j][1] + bv.y, 0.f);
            float v2 = fmaxf(acc[mi][j][2] + bv.x, 0.f);
            float v3 = fmaxf(acc[mi][j][3] + bv.y, 0.f);
            if (SPLIT) {
                uint32_t hp, lp;
                if (r1 < M) {
                    split2(v0, v1, hp, lp);
                    Chi[(size_t)r1 * (NT / 2) + gcol / 2] = hp;
                    Clo[(size_t)r1 * (NT / 2) + gcol / 2] = lp;
                }
                if (r2 < M) {
                    split2(v2, v3, hp, lp);
                    Chi[(size_t)r2 * (NT / 2) + gcol / 2] = hp;
                    Clo[(size_t)r2 * (NT / 2) + gcol / 2] = lp;
                }
            } else {
                if (r1 < M) *(float2*)(Cf + (size_t)r1 * NT + gcol) = make_float2(v0, v1);
                if (r2 < M) *(float2*)(Cf + (size_t)r2 * NT + gcol) = make_float2(v2, v3);
            }
        }
    }
}

// ======================= SIMT f32x2 GEMM (agent MLP) =======================
__device__ __forceinline__ ull pk2(float a) {
    ull r; unsigned u = __float_as_uint(a);
    asm("mov.b64 %0, {%1, %2};" : "=l"(r) : "r"(u), "r"(u));
    return r;
}
__device__ __forceinline__ ull pkp(float x, float y) {
    ull r;
    asm("mov.b64 %0, {%1, %2};" : "=l"(r)
        : "r"(__float_as_uint(x)), "r"(__float_as_uint(y)));
    return r;
}
__device__ __forceinline__ void fma2(ull& d, ull a, ull b) {
    asm("fma.rn.f32x2 %0, %1, %2, %0;" : "+l"(d) : "l"(a), "l"(b));
}
__device__ __forceinline__ float2 upk(ull v) {
    float2 r;
    asm("mov.b64 {%0, %1}, %2;" : "=f"(r.x), "=f"(r.y) : "l"(v));
    return r;
}

#define BM 128
#define BN 128
#define BK 16

template<int KD, int NT, bool RELU>
__global__ __launch_bounds__(256, 2)
void gemm_k(const float* __restrict__ A,
            const float* __restrict__ B,
            const float* __restrict__ bias,
            float*       __restrict__ C,
            const int*   __restrict__ mptr)
{
    const int M = *mptr;
    const int row0 = blockIdx.x * BM;
    if (row0 >= M) return;
    const int n0  = blockIdx.y * BN;
    const int tid = threadIdx.x;

    __shared__ float As[2][BK][BM];
    __shared__ float Bs[2][BK][BN];

    const int a_m  = tid >> 1;
    const int a_k0 = (tid & 1) * 8;
    const int b_k  = tid >> 4;
    const int b_n  = (tid & 15) * 8;

    float4 ra[2], rb[2];

    auto loadA = [&](int kb) {
        #pragma unroll
        for (int i = 0; i < 2; ++i) {
            int k   = kb * BK + a_k0 + i * 4;
            int row = row0 + a_m;
            ra[i] = (row < M) ? *(const float4*)(A + (size_t)row * KD + k)
                              : make_float4(0.f, 0.f, 0.f, 0.f);
        }
    };
    auto loadB = [&](int kb) {
        #pragma unroll
        for (int i = 0; i < 2; ++i) {
            int k = kb * BK + b_k;
            rb[i] = *(const float4*)(B + (size_t)k * NT + n0 + b_n + i * 4);
        }
    };
    auto stash = [&](int b) {
        #pragma unroll
        for (int i = 0; i < 2; ++i) {
            int kl = a_k0 + i * 4;
            As[b][kl    ][a_m] = ra[i].x;
            As[b][kl + 1][a_m] = ra[i].y;
            As[b][kl + 2][a_m] = ra[i].z;
            As[b][kl + 3][a_m] = ra[i].w;
            *(float4*)&Bs[b][b_k][b_n + i * 4] = rb[i];
        }
    };

    loadA(0); loadB(0);
    stash(0);
    __syncthreads();

    ull acc[8][4] = {};
    const int my = (tid >> 4) * 8;
    const int nx = (tid & 15) * 8;
    constexpr int NKB = KD / BK;
    int buf = 0;

    #pragma unroll 1
    for (int kb = 0; kb < NKB; ++kb) {
        if (kb + 1 < NKB) { loadA(kb + 1); loadB(kb + 1); }
        #pragma unroll
        for (int k = 0; k < BK; ++k) {
            float4 A0 = *(const float4*)&As[buf][k][my];
            float4 A1 = *(const float4*)&As[buf][k][my + 4];
            float4 B0 = *(const float4*)&Bs[buf][k][nx];
            float4 B1 = *(const float4*)&Bs[buf][k][nx + 4];
            ull bb0 = pkp(B0.x, B0.y), bb1 = pkp(B0.z, B0.w);
            ull bb2 = pkp(B1.x, B1.y), bb3 = pkp(B1.z, B1.w);
            float av[8] = {A0.x, A0.y, A0.z, A0.w, A1.x, A1.y, A1.z, A1.w};
            #pragma unroll
            for (int r = 0; r < 8; ++r) {
                ull ar = pk2(av[r]);
                fma2(acc[r][0], ar, bb0);
                fma2(acc[r][1], ar, bb1);
                fma2(acc[r][2], ar, bb2);
                fma2(acc[r][3], ar, bb3);
            }
        }
        if (kb + 1 < NKB) {
            stash(buf ^ 1);
            __syncthreads();
            buf ^= 1;
        }
    }

    float bv[8];
    #pragma unroll
    for (int j = 0; j < 8; ++j) bv[j] = bias[n0 + nx + j];

    #pragma unroll
    for (int r = 0; r < 8; ++r) {
        int row = row0 + my + r;
        if (row < M) {
            float o[8];
            #pragma unroll
            for (int c = 0; c < 4; ++c) {
                float2 v = upk(acc[r][c]);
                o[2 * c]     = v.x + bv[2 * c];
                o[2 * c + 1] = v.y + bv[2 * c + 1];
            }
            if (RELU) {
                #pragma unroll
                for (int j = 0; j < 8; ++j) o[j] = fmaxf(o[j], 0.f);
            }
            float* cp = C + (size_t)row * NT + n0 + nx;
            *(float4*)cp       = make_float4(o[0], o[1], o[2], o[3]);
            *(float4*)(cp + 4) = make_float4(o[4], o[5], o[6], o[7]);
        }
    }
}

// ======================= small kernels =====================================
__device__ __forceinline__ unsigned fmap(float f) {
    unsigned u = __float_as_uint(f);
    return (u & 0x80000000u) ? ~u : (u | 0x80000000u);
}
__device__ __forceinline__ float funmap(unsigned u) {
    return __uint_as_float((u & 0x80000000u) ? (u ^ 0x80000000u) : ~u);
}

__global__ void init_k(int n_nodes) {
    int i = blockIdx.x * blockDim.x + threadIdx.x;
    if (i < n_nodes * 128) g_aggr[i] = 0.f;
    if (i < n_nodes) { g_denom[i] = 0.f; g_segmax[i] = 0u; }
    if (i == 0) g_count[0] = 0;
}

// Warp-aggregated compaction of edges with receiver < n_agents.
__global__ void compact_k(const int* __restrict__ receivers,
                          const int* __restrict__ nag, int n_edges) {
    int e = blockIdx.x * blockDim.x + threadIdx.x;
    int lane = threadIdx.x & 31;
    int r = (e < n_edges) ? receivers[e] : 0x7fffffff;
    bool act = (e < n_edges) && (r < *nag);
    unsigned m = __ballot_sync(0xffffffffu, act);
    if (!m) return;
    int leader = __ffs(m) - 1;
    int base = 0;
    if (lane == leader) base = atomicAdd(g_count, __popc(m));
    base = __shfl_sync(0xffffffffu, base, leader);
    if (act) {
        int pos = base + __popc(m & ((1u << lane) - 1u));
        g_eidx[pos] = e;
        g_rcvc[pos] = r;
    }
}

__global__ void logits_k(const float* __restrict__ w_gate,
                         const float* __restrict__ b_gate) {
    int idx  = blockIdx.x * blockDim.x + threadIdx.x;
    int row  = idx >> 5, lane = idx & 31;
    if (row >= g_count[0]) return;
    float4 m4 = *(const float4*)(g_MSG + (size_t)row * 128 + lane * 4);
    float4 g4 = *(const float4*)(w_gate + lane * 4);
    float s = m4.x * g4.x + m4.y * g4.y + m4.z * g4.z + m4.w * g4.w;
    #pragma unroll
    for (int o = 16; o; o >>= 1) s += __shfl_xor_sync(0xffffffffu, s, o);
    if (lane == 0) {
        float lg = s + b_gate[0];
        g_logits[row] = lg;
        atomicMax(&g_segmax[g_rcvc[row]], fmap(lg));
    }
}

__global__ void aggr_k() {
    int idx = blockIdx.x * blockDim.x + threadIdx.x;
    int row = idx >> 5, lane = idx & 31;
    if (row >= g_count[0]) return;
    int rv = g_rcvc[row];
    float w = expf(g_logits[row] - funmap(g_segmax[rv]));
    if (lane == 0) atomicAdd(&g_denom[rv], w);
    float4 m4 = *(const float4*)(g_MSG + (size_t)row * 128 + lane * 4);
    float* dst = g_aggr + (size_t)rv * 128 + lane * 4;
    asm volatile("red.global.add.v4.f32 [%0], {%1, %2, %3, %4};"
                 :: "l"(dst), "f"(m4.x * w), "f"(m4.y * w),
                    "f"(m4.z * w), "f"(m4.w * w)
                 : "memory");
}

__global__ void norm_k(const int* __restrict__ nag, int n_nodes) {
    int i = blockIdx.x * blockDim.x + threadIdx.x;
    if (i >= n_nodes * 128) return;
    int row = i >> 7;
    if (row < *nag) g_X0[i] = g_aggr[i] / (g_denom[row] + 1e-9f);
}

__global__ void out_k(const float* __restrict__ W, const float* __restrict__ b,
                      const int* __restrict__ nag, float* __restrict__ out) {
    int idx = blockIdx.x * blockDim.x + threadIdx.x;
    int row = idx >> 5, lane = idx & 31;
    if (row >= *nag) return;
    const float4* xr = (const float4*)(g_X2 + (size_t)row * 256);
    const float4* wr = (const float4*)W;
    float s = 0.f;
    #pragma unroll
    for (int j = 0; j < 2; ++j) {
        float4 x = xr[lane + 32 * j], wv = wr[lane + 32 * j];
        s += x.x * wv.x + x.y * wv.y + x.z * wv.z + x.w * wv.w;
    }
    #pragma unroll
    for (int o = 16; o; o >>= 1) s += __shfl_xor_sync(0xffffffffu, s, o);
    if (lane == 0) out[row] = tanhf(s + b[0]);
}

// ---------------------------------------------------------------------------
extern "C" void kernel_launch(void* const* d_in, const int* in_sizes, int n_in,
                              void* d_out, int out_size)
{
    const float* node_feats = (const float*)d_in[0];
    const float* edge_feats = (const float*)d_in[1];
    const float* W_msg1 = (const float*)d_in[2];
    const float* b_msg1 = (const float*)d_in[3];
    const float* W_msg2 = (const float*)d_in[4];
    const float* b_msg2 = (const float*)d_in[5];
    const float* w_gate = (const float*)d_in[6];
    const float* b_gate = (const float*)d_in[7];
    const float* W_h1   = (const float*)d_in[8];
    const float* b_h1   = (const float*)d_in[9];
    const float* W_h2   = (const float*)d_in[10];
    const float* b_h2   = (const float*)d_in[11];
    const float* W_out  = (const float*)d_in[12];
    const float* b_out  = (const float*)d_in[13];
    const int*   senders   = (const int*)d_in[14];
    const int*   receivers = (const int*)d_in[15];
    const int*   nag       = (const int*)d_in[16];
    float* out = (float*)d_out;

    int n_nodes = in_sizes[0] / 64;
    int n_edges = in_sizes[14];

    uint32_t *pAhi, *pAlo, *pHhi, *pHlo;
    float *pMSG, *pX0, *pX1, *pX2;
    __nv_bfloat16 *pW1h, *pW1l, *pW2h, *pW2l;
    int *pcount;
    cudaGetSymbolAddress((void**)&pAhi,   g_Ahi);
    cudaGetSymbolAddress((void**)&pAlo,   g_Alo);
    cudaGetSymbolAddress((void**)&pHhi,   g_Hhi);
    cudaGetSymbolAddress((void**)&pHlo,   g_Hlo);
    cudaGetSymbolAddress((void**)&pMSG,   g_MSG);
    cudaGetSymbolAddress((void**)&pX0,    g_X0);
    cudaGetSymbolAddress((void**)&pX1,    g_X1);
    cudaGetSymbolAddress((void**)&pX2,    g_X2);
    cudaGetSymbolAddress((void**)&pW1h,   g_W1Thi);
    cudaGetSymbolAddress((void**)&pW1l,   g_W1Tlo);
    cudaGetSymbolAddress((void**)&pW2h,   g_W2Thi);
    cudaGetSymbolAddress((void**)&pW2l,   g_W2Tlo);
    cudaGetSymbolAddress((void**)&pcount, g_count);

    const int DSMEM = 2 * (2 * 2 * 128 * APAD) * 2;  // A + B regions, bytes = 81920
    auto* g1 = &mma_gemm<160, 256, true>;
    auto* g2 = &mma_gemm<256, 128, false>;
    cudaFuncSetAttribute(g1, cudaFuncAttributeMaxDynamicSharedMemorySize, DSMEM);
    cudaFuncSetAttribute(g2, cudaFuncAttributeMaxDynamicSharedMemorySize, DSMEM);

    const int t = 256;
    prepW_k<<<(160 * 256 + t - 1) / t, t>>>(W_msg1, pW1h, pW1l, 160, 256);
    prepW_k<<<(256 * 128 + t - 1) / t, t>>>(W_msg2, pW2h, pW2l, 256, 128);
    init_k<<<(n_nodes * 128 + t - 1) / t, t>>>(n_nodes);
    compact_k<<<(n_edges + t - 1) / t, t>>>(receivers, nag, n_edges);
    convertA_k<<<((size_t)n_edges * 40 + t - 1) / t, t>>>(node_feats, edge_feats,
                                                          senders, receivers, n_edges);

    int mtiles = (n_edges + 127) / 128;
    mma_gemm<160, 256, true><<<dim3(mtiles, 2), 256, DSMEM>>>(
        (const __nv_bfloat16*)pAhi, (const __nv_bfloat16*)pAlo,
        pW1h, pW1l, b_msg1, pHhi, pHlo, nullptr, pcount);
    mma_gemm<256, 128, false><<<dim3(mtiles, 1), 256, DSMEM>>>(
        (const __nv_bfloat16*)pHhi, (const __nv_bfloat16*)pHlo,
        pW2h, pW2l, b_msg2, nullptr, nullptr, pMSG, pcount);

    logits_k<<<(n_edges * 32 + t - 1) / t, t>>>(w_gate, b_gate);
    aggr_k<<<(n_edges * 32 + t - 1) / t, t>>>();
    norm_k<<<(n_nodes * 128 + t - 1) / t, t>>>(nag, n_nodes);

    dim3 g3((n_nodes + BM - 1) / BM, 2);
    gemm_k<128, 256, true><<<g3, 256>>>(pX0, W_h1, b_h1, pX1, nag);
    gemm_k<256, 256, true><<<g3, 256>>>(pX1, W_h2, b_h2, pX2, nag);
    out_k<<<(n_nodes * 32 + t - 1) / t, t>>>(W_out, b_out, nag, out);
}

// round 12
// speedup vs baseline: 1.2717x; 1.0150x over previous
#include <cuda_runtime.h>
#include <cuda_bf16.h>
#include <cstdint>
#include <cstddef>

// ---------------------------------------------------------------------------
// CBFNet on GB300 (compute_103 — no tcgen05, no cp.async):
//   compact dead edges -> gather+split convert -> bf16 3-term-split HMMA
//   edge MLP (CTA 128x64, occ-2, ldmatrix frags) -> gated segment softmax
//   (folded norm, vector RED) -> agent MLP (f32x2).
// ---------------------------------------------------------------------------

#define MAXE 800000
#define MAXN 50000

typedef unsigned long long ull;

// Scratch (allocation-free rule: __device__ globals)
__device__ uint32_t g_Ahi[(size_t)MAXE * 80];    // gathered A, bf16x2 hi plane [m][160]
__device__ uint32_t g_Alo[(size_t)MAXE * 80];    // lo plane
__device__ uint32_t g_Hhi[(size_t)MAXE * 128];   // H bf16x2 hi plane [m][256]
__device__ uint32_t g_Hlo[(size_t)MAXE * 128];   // lo plane
__device__ float    g_MSG[(size_t)MAXE * 128];
__device__ float    g_logits[MAXE];
__device__ int      g_eidx[MAXE];
__device__ int      g_rcvc[MAXE];
__device__ unsigned g_segmax[MAXN];
__device__ float    g_denom[MAXN];
__device__ float    g_aggr[(size_t)MAXN * 128];
__device__ float    g_X0[(size_t)MAXN * 128];
__device__ float    g_X1[(size_t)MAXN * 256];
__device__ float    g_X2[(size_t)MAXN * 256];
__device__ int      g_count[1];

// Transposed bf16 weight planes [N][K] (row.col mma layout: B^T rows k-contig)
__device__ __nv_bfloat16 g_W1Thi[256 * 160];
__device__ __nv_bfloat16 g_W1Tlo[256 * 160];
__device__ __nv_bfloat16 g_W2Thi[128 * 256];
__device__ __nv_bfloat16 g_W2Tlo[128 * 256];

// ============================ helpers ======================================
__device__ __forceinline__ uint32_t smem_u32(const void* p) {
    uint32_t a;
    asm("{ .reg .u64 t; cvta.to.shared.u64 t, %1; cvt.u32.u64 %0, t; }"
        : "=r"(a) : "l"(p));
    return a;
}

// fp32 pair -> packed bf16x2 hi/lo planes
__device__ __forceinline__ void split2(float a, float b, uint32_t& hp, uint32_t& lp) {
    __nv_bfloat16 ha = __float2bfloat16(a), hb = __float2bfloat16(b);
    __nv_bfloat16 la = __float2bfloat16(a - __bfloat162float(ha));
    __nv_bfloat16 lb = __float2bfloat16(b - __bfloat162float(hb));
    hp = ((uint32_t)__bfloat16_as_ushort(hb) << 16) | __bfloat16_as_ushort(ha);
    lp = ((uint32_t)__bfloat16_as_ushort(lb) << 16) | __bfloat16_as_ushort(la);
}

__device__ __forceinline__ void mma16816(float* c, const uint32_t* a, const uint32_t* b) {
    asm volatile(
        "mma.sync.aligned.m16n8k16.row.col.f32.bf16.bf16.f32 "
        "{%0,%1,%2,%3}, {%4,%5,%6,%7}, {%8,%9}, {%0,%1,%2,%3};"
        : "+f"(c[0]), "+f"(c[1]), "+f"(c[2]), "+f"(c[3])
        : "r"(a[0]), "r"(a[1]), "r"(a[2]), "r"(a[3]), "r"(b[0]), "r"(b[1]));
}

#define LDSM_X4(r0, r1, r2, r3, addr) \
    asm volatile("ldmatrix.sync.aligned.m8n8.x4.shared.b16 {%0,%1,%2,%3}, [%4];" \
        : "=r"(r0), "=r"(r1), "=r"(r2), "=r"(r3) : "r"(addr))

// ======================= prep kernels ======================================
__global__ void prepW_k(const float* __restrict__ W,
                        __nv_bfloat16* __restrict__ Thi,
                        __nv_bfloat16* __restrict__ Tlo, int K, int N) {
    int i = blockIdx.x * blockDim.x + threadIdx.x;
    if (i >= K * N) return;
    int n = i / K, k = i % K;
    float v = W[k * N + n];
    __nv_bfloat16 h = __float2bfloat16(v);
    Thi[n * K + k] = h;
    Tlo[n * K + k] = __float2bfloat16(v - __bfloat162float(h));
}

// Gather [sender||receiver||edge] fp32 rows -> packed bf16 hi/lo planes [m][160]
__global__ void convertA_k(const float* __restrict__ nodef,
                           const float* __restrict__ edgef,
                           const int*   __restrict__ senders,
                           const int*   __restrict__ receivers, int n_edges) {
    int i = blockIdx.x * blockDim.x + threadIdx.x;
    int row = i / 40, q = i % 40;
    if (row >= g_count[0]) return;
    int e = g_eidx[row];
    int pos = q * 4;
    const float* src;
    if (pos < 64)       src = nodef + (size_t)senders[e] * 64 + pos;
    else if (pos < 128) src = nodef + (size_t)receivers[e] * 64 + (pos - 64);
    else                src = edgef + (size_t)e * 32 + (pos - 128);
    float4 f = *(const float4*)src;
    uint32_t h0, l0, h1, l1;
    split2(f.x, f.y, h0, l0);
    split2(f.z, f.w, h1, l1);
    size_t o = (size_t)row * 80 + q * 2;
    g_Ahi[o] = h0; g_Ahi[o + 1] = h1;
    g_Alo[o] = l0; g_Alo[o + 1] = l1;
}

// ======================= HMMA 3-term-split GEMM ============================
// C[M, NT] = relu(A @ B + bias); A bf16 hi/lo planes [M][KD] row-major,
// B bf16 hi/lo planes [NT][KD]. CTA 128x64 (grid.y = NT/64), 8 warps 4(M)x2(N),
// warp tile 32x32, BK=32, occ-2 (__launch_bounds__(256,2)), register-staged
// double-buffered smem, ldmatrix.x4 fragment loads, +8 pad (conflict-free).
// 3 mma passes: hi*hi + hi*lo + lo*hi (fp32 accum).
#define APAD 40   // 32 + 8 pad (bf16 elems per smem row)

template<int KD, int NT, bool SPLIT>
__global__ __launch_bounds__(256, 2)
void mma_gemm(const __nv_bfloat16* __restrict__ Ahi,
              const __nv_bfloat16* __restrict__ Alo,
              const __nv_bfloat16* __restrict__ Bhi,
              const __nv_bfloat16* __restrict__ Blo,
              const float*    __restrict__ bias,
              uint32_t*       __restrict__ Chi,
              uint32_t*       __restrict__ Clo,
              float*          __restrict__ Cf,
              const int*      __restrict__ mptr)
{
    const int M = *mptr;
    const int row0 = blockIdx.x * 128;
    if (row0 >= M) return;
    const int n0  = blockIdx.y * 64;
    const int tid  = threadIdx.x;
    const int lane = tid & 31, wid = tid >> 5;
    const int gq = lane >> 2, tq = lane & 3;
    const int wr = (wid & 3) * 32;      // warp row base (M)
    const int wc = (wid >> 2) * 32;     // warp col base (N, within 64)

    extern __shared__ char dsm[];
    __nv_bfloat16* S = (__nv_bfloat16*)dsm;
    const uint32_t sbase = smem_u32(dsm);
    // bf16-elem layout: A planes [buf*2+p][128][APAD] at 0; B planes at BOFF
    const int BOFF = 2 * 2 * 128 * APAD;   // 20480 elems

    // Fill mapping. A: 512 16B-chunks / 256 thr = 2 each. B: 256 chunks = 1 each.
    const int fa_r0 = (tid * 2)     >> 2, fa_k0 = ((tid * 2)     & 3) * 8;
    const int fa_r1 = (tid * 2 + 1) >> 2, fa_k1 = ((tid * 2 + 1) & 3) * 8;
    const int fb_r  = tid >> 2,           fb_k  = (tid & 3) * 8;

    uint4 stA[2][2], stB[2];

    auto gload = [&](int kb) {
        #pragma unroll
        for (int p = 0; p < 2; ++p) {
            const __nv_bfloat16* A_ = p ? Alo : Ahi;
            const __nv_bfloat16* B_ = p ? Blo : Bhi;
            stA[p][0] = *(const uint4*)(A_ + (size_t)(row0 + fa_r0) * KD + kb * 32 + fa_k0);
            stA[p][1] = *(const uint4*)(A_ + (size_t)(row0 + fa_r1) * KD + kb * 32 + fa_k1);
            stB[p]    = *(const uint4*)(B_ + (size_t)(n0  + fb_r)  * KD + kb * 32 + fb_k);
        }
    };
    auto sstore = [&](int b) {
        #pragma unroll
        for (int p = 0; p < 2; ++p) {
            *(uint4*)(S + ((b * 2 + p) * 128 + fa_r0) * APAD + fa_k0) = stA[p][0];
            *(uint4*)(S + ((b * 2 + p) * 128 + fa_r1) * APAD + fa_k1) = stA[p][1];
            *(uint4*)(S + BOFF + ((b * 2 + p) * 64 + fb_r) * APAD + fb_k) = stB[p];
        }
    };

    // ldmatrix per-thread address components (bf16-elem offsets)
    const int lm  = lane >> 3, lr = lane & 7;
    const int aRow = wr + (lm & 1) * 8 + lr;   // + mi*16
    const int aCol = (lm >> 1) * 8;            // + kk
    const int bRow = wc + (lm >> 1) * 8 + lr;  // + jblk*16
    const int bCol = (lm & 1) * 8;             // + kk

    float acc[2][4][4];
    #pragma unroll
    for (int mi = 0; mi < 2; ++mi)
        #pragma unroll
        for (int j = 0; j < 4; ++j)
            #pragma unroll
            for (int q = 0; q < 4; ++q) acc[mi][j][q] = 0.f;

    constexpr int NKB = KD / 32;
    int buf = 0;

    gload(0);
    sstore(0);
    __syncthreads();

    #pragma unroll 1
    for (int kb = 0; kb < NKB; ++kb) {
        if (kb + 1 < NKB) gload(kb + 1);

        #pragma unroll
        for (int kk = 0; kk < 32; kk += 16) {
            uint32_t af[2][2][4], bf[2][4][2];
            #pragma unroll
            for (int p = 0; p < 2; ++p) {
                uint32_t ab = sbase + ((buf * 2 + p) * 128 * APAD) * 2;
                #pragma unroll
                for (int mi = 0; mi < 2; ++mi) {
                    uint32_t ad = ab + (((aRow + mi * 16) * APAD) + kk + aCol) * 2;
                    LDSM_X4(af[p][mi][0], af[p][mi][1], af[p][mi][2], af[p][mi][3], ad);
                }
                uint32_t bb = sbase + (BOFF + (buf * 2 + p) * 64 * APAD) * 2;
                #pragma unroll
                for (int jb = 0; jb < 2; ++jb) {
                    uint32_t bd = bb + (((bRow + jb * 16) * APAD) + kk + bCol) * 2;
                    LDSM_X4(bf[p][2 * jb][0], bf[p][2 * jb][1],
                            bf[p][2 * jb + 1][0], bf[p][2 * jb + 1][1], bd);
                }
            }
            #pragma unroll
            for (int mi = 0; mi < 2; ++mi)
                #pragma unroll
                for (int j = 0; j < 4; ++j) {
                    mma16816(acc[mi][j], af[0][mi], bf[0][j]);  // hi*hi
                    mma16816(acc[mi][j], af[0][mi], bf[1][j]);  // hi*lo
                    mma16816(acc[mi][j], af[1][mi], bf[0][j]);  // lo*hi
                }
        }

        if (kb + 1 < NKB) {
            sstore(buf ^ 1);
            __syncthreads();
            buf ^= 1;
        }
    }

    // Epilogue: bias + relu; SPLIT -> bf16 hi/lo planes, else fp32
    #pragma unroll
    for (int mi = 0; mi < 2; ++mi) {
        int r1 = row0 + wr + mi * 16 + gq;
        int r2 = r1 + 8;
        #pragma unroll
        for (int j = 0; j < 4; ++j) {
            int gcol = n0 + wc + j * 8 + tq * 2;
            float2 bv = *(const float2*)(bias + gcol);
            float v0 = fmaxf(acc[mi][j][0] + bv.x, 0.f);
            float v1 = fmaxf(acc[mi][j][1] + bv.y, 0.f);
            float v2 = fmaxf(acc[mi][j][2] + bv.x, 0.f);
            float v3 = fmaxf(acc[mi][j][3] + bv.y, 0.f);
            if (SPLIT) {
                uint32_t hp, lp;
                if (r1 < M) {
                    split2(v0, v1, hp, lp);
                    Chi[(size_t)r1 * (NT / 2) + gcol / 2] = hp;
                    Clo[(size_t)r1 * (NT / 2) + gcol / 2] = lp;
                }
                if (r2 < M) {
                    split2(v2, v3, hp, lp);
                    Chi[(size_t)r2 * (NT / 2) + gcol / 2] = hp;
                    Clo[(size_t)r2 * (NT / 2) + gcol / 2] = lp;
                }
            } else {
                if (r1 < M) *(float2*)(Cf + (size_t)r1 * NT + gcol) = make_float2(v0, v1);
                if (r2 < M) *(float2*)(Cf + (size_t)r2 * NT + gcol) = make_float2(v2, v3);
            }
        }
    }
}

// ======================= SIMT f32x2 GEMM (agent MLP) =======================
__device__ __forceinline__ ull pk2(float a) {
    ull r; unsigned u = __float_as_uint(a);
    asm("mov.b64 %0, {%1, %2};" : "=l"(r) : "r"(u), "r"(u));
    return r;
}
__device__ __forceinline__ ull pkp(float x, float y) {
    ull r;
    asm("mov.b64 %0, {%1, %2};" : "=l"(r)
        : "r"(__float_as_uint(x)), "r"(__float_as_uint(y)));
    return r;
}
__device__ __forceinline__ void fma2(ull& d, ull a, ull b) {
    asm("fma.rn.f32x2 %0, %1, %2, %0;" : "+l"(d) : "l"(a), "l"(b));
}
__device__ __forceinline__ float2 upk(ull v) {
    float2 r;
    asm("mov.b64 {%0, %1}, %2;" : "=f"(r.x), "=f"(r.y) : "l"(v));
    return r;
}

#define BM 128
#define BN 128
#define BK 16

template<int KD, int NT, bool RELU>
__global__ __launch_bounds__(256, 2)
void gemm_k(const float* __restrict__ A,
            const float* __restrict__ B,
            const float* __restrict__ bias,
            float*       __restrict__ C,
            const int*   __restrict__ mptr)
{
    const int M = *mptr;
    const int row0 = blockIdx.x * BM;
    if (row0 >= M) return;
    const int n0  = blockIdx.y * BN;
    const int tid = threadIdx.x;

    __shared__ float As[2][BK][BM];
    __shared__ float Bs[2][BK][BN];

    const int a_m  = tid >> 1;
    const int a_k0 = (tid & 1) * 8;
    const int b_k  = tid >> 4;
    const int b_n  = (tid & 15) * 8;

    float4 ra[2], rb[2];

    auto loadA = [&](int kb) {
        #pragma unroll
        for (int i = 0; i < 2; ++i) {
            int k   = kb * BK + a_k0 + i * 4;
            int row = row0 + a_m;
            ra[i] = (row < M) ? *(const float4*)(A + (size_t)row * KD + k)
                              : make_float4(0.f, 0.f, 0.f, 0.f);
        }
    };
    auto loadB = [&](int kb) {
        #pragma unroll
        for (int i = 0; i < 2; ++i) {
            int k = kb * BK + b_k;
            rb[i] = *(const float4*)(B + (size_t)k * NT + n0 + b_n + i * 4);
        }
    };
    auto stash = [&](int b) {
        #pragma unroll
        for (int i = 0; i < 2; ++i) {
            int kl = a_k0 + i * 4;
            As[b][kl    ][a_m] = ra[i].x;
            As[b][kl + 1][a_m] = ra[i].y;
            As[b][kl + 2][a_m] = ra[i].z;
            As[b][kl + 3][a_m] = ra[i].w;
            *(float4*)&Bs[b][b_k][b_n + i * 4] = rb[i];
        }
    };

    loadA(0); loadB(0);
    stash(0);
    __syncthreads();

    ull acc[8][4] = {};
    const int my = (tid >> 4) * 8;
    const int nx = (tid & 15) * 8;
    constexpr int NKB = KD / BK;
    int buf = 0;

    #pragma unroll 1
    for (int kb = 0; kb < NKB; ++kb) {
        if (kb + 1 < NKB) { loadA(kb + 1); loadB(kb + 1); }
        #pragma unroll
        for (int k = 0; k < BK; ++k) {
            float4 A0 = *(const float4*)&As[buf][k][my];
            float4 A1 = *(const float4*)&As[buf][k][my + 4];
            float4 B0 = *(const float4*)&Bs[buf][k][nx];
            float4 B1 = *(const float4*)&Bs[buf][k][nx + 4];
            ull bb0 = pkp(B0.x, B0.y), bb1 = pkp(B0.z, B0.w);
            ull bb2 = pkp(B1.x, B1.y), bb3 = pkp(B1.z, B1.w);
            float av[8] = {A0.x, A0.y, A0.z, A0.w, A1.x, A1.y, A1.z, A1.w};
            #pragma unroll
            for (int r = 0; r < 8; ++r) {
                ull ar = pk2(av[r]);
                fma2(acc[r][0], ar, bb0);
                fma2(acc[r][1], ar, bb1);
                fma2(acc[r][2], ar, bb2);
                fma2(acc[r][3], ar, bb3);
            }
        }
        if (kb + 1 < NKB) {
            stash(buf ^ 1);
            __syncthreads();
            buf ^= 1;
        }
    }

    float bv[8];
    #pragma unroll
    for (int j = 0; j < 8; ++j) bv[j] = bias[n0 + nx + j];

    #pragma unroll
    for (int r = 0; r < 8; ++r) {
        int row = row0 + my + r;
        if (row < M) {
            float o[8];
            #pragma unroll
            for (int c = 0; c < 4; ++c) {
                float2 v = upk(acc[r][c]);
                o[2 * c]     = v.x + bv[2 * c];
                o[2 * c + 1] = v.y + bv[2 * c + 1];
            }
            if (RELU) {
                #pragma unroll
                for (int j = 0; j < 8; ++j) o[j] = fmaxf(o[j], 0.f);
            }
            float* cp = C + (size_t)row * NT + n0 + nx;
            *(float4*)cp       = make_float4(o[0], o[1], o[2], o[3]);
            *(float4*)(cp + 4) = make_float4(o[4], o[5], o[6], o[7]);
        }
    }
}

// ======================= small kernels =====================================
__device__ __forceinline__ unsigned fmap(float f) {
    unsigned u = __float_as_uint(f);
    return (u & 0x80000000u) ? ~u : (u | 0x80000000u);
}
__device__ __forceinline__ float funmap(unsigned u) {
    return __uint_as_float((u & 0x80000000u) ? (u ^ 0x80000000u) : ~u);
}

__global__ void init_k(int n_nodes) {
    int i = blockIdx.x * blockDim.x + threadIdx.x;
    if (i < n_nodes * 128) g_aggr[i] = 0.f;
    if (i < n_nodes) { g_denom[i] = 0.f; g_segmax[i] = 0u; }
    if (i == 0) g_count[0] = 0;
}

// Warp-aggregated compaction of edges with receiver < n_agents.
__global__ void compact_k(const int* __restrict__ receivers,
                          const int* __restrict__ nag, int n_edges) {
    int e = blockIdx.x * blockDim.x + threadIdx.x;
    int lane = threadIdx.x & 31;
    int r = (e < n_edges) ? receivers[e] : 0x7fffffff;
    bool act = (e < n_edges) && (r < *nag);
    unsigned m = __ballot_sync(0xffffffffu, act);
    if (!m) return;
    int leader = __ffs(m) - 1;
    int base = 0;
    if (lane == leader) base = atomicAdd(g_count, __popc(m));
    base = __shfl_sync(0xffffffffu, base, leader);
    if (act) {
        int pos = base + __popc(m & ((1u << lane) - 1u));
        g_eidx[pos] = e;
        g_rcvc[pos] = r;
    }
}

__global__ void logits_k(const float* __restrict__ w_gate,
                         const float* __restrict__ b_gate) {
    int idx  = blockIdx.x * blockDim.x + threadIdx.x;
    int row  = idx >> 5, lane = idx & 31;
    if (row >= g_count[0]) return;
    float4 m4 = *(const float4*)(g_MSG + (size_t)row * 128 + lane * 4);
    float4 g4 = *(const float4*)(w_gate + lane * 4);
    float s = m4.x * g4.x + m4.y * g4.y + m4.z * g4.z + m4.w * g4.w;
    #pragma unroll
    for (int o = 16; o; o >>= 1) s += __shfl_xor_sync(0xffffffffu, s, o);
    if (lane == 0) {
        float lg = s + b_gate[0];
        g_logits[row] = lg;
        atomicMax(&g_segmax[g_rcvc[row]], fmap(lg));
    }
}

__global__ void aggr_k() {
    int idx = blockIdx.x * blockDim.x + threadIdx.x;
    int row = idx >> 5, lane = idx & 31;
    if (row >= g_count[0]) return;
    int rv = g_rcvc[row];
    float w = expf(g_logits[row] - funmap(g_segmax[rv]));
    if (lane == 0) atomicAdd(&g_denom[rv], w);
    float4 m4 = *(const float4*)(g_MSG + (size_t)row * 128 + lane * 4);
    float* dst = g_aggr + (size_t)rv * 128 + lane * 4;
    asm volatile("red.global.add.v4.f32 [%0], {%1, %2, %3, %4};"
                 :: "l"(dst), "f"(m4.x * w), "f"(m4.y * w),
                    "f"(m4.z * w), "f"(m4.w * w)
                 : "memory");
}

__global__ void norm_k(const int* __restrict__ nag, int n_nodes) {
    int i = blockIdx.x * blockDim.x + threadIdx.x;
    if (i >= n_nodes * 128) return;
    int row = i >> 7;
    if (row < *nag) g_X0[i] = g_aggr[i] / (g_denom[row] + 1e-9f);
}

__global__ void out_k(const float* __restrict__ W, const float* __restrict__ b,
                      const int* __restrict__ nag, float* __restrict__ out) {
    int idx = blockIdx.x * blockDim.x + threadIdx.x;
    int row = idx >> 5, lane = idx & 31;
    if (row >= *nag) return;
    const float4* xr = (const float4*)(g_X2 + (size_t)row * 256);
    const float4* wr = (const float4*)W;
    float s = 0.f;
    #pragma unroll
    for (int j = 0; j < 2; ++j) {
        float4 x = xr[lane + 32 * j], wv = wr[lane + 32 * j];
        s += x.x * wv.x + x.y * wv.y + x.z * wv.z + x.w * wv.w;
    }
    #pragma unroll
    for (int o = 16; o; o >>= 1) s += __shfl_xor_sync(0xffffffffu, s, o);
    if (lane == 0) out[row] = tanhf(s + b[0]);
}

// ---------------------------------------------------------------------------
extern "C" void kernel_launch(void* const* d_in, const int* in_sizes, int n_in,
                              void* d_out, int out_size)
{
    const float* node_feats = (const float*)d_in[0];
    const float* edge_feats = (const float*)d_in[1];
    const float* W_msg1 = (const float*)d_in[2];
    const float* b_msg1 = (const float*)d_in[3];
    const float* W_msg2 = (const float*)d_in[4];
    const float* b_msg2 = (const float*)d_in[5];
    const float* w_gate = (const float*)d_in[6];
    const float* b_gate = (const float*)d_in[7];
    const float* W_h1   = (const float*)d_in[8];
    const float* b_h1   = (const float*)d_in[9];
    const float* W_h2   = (const float*)d_in[10];
    const float* b_h2   = (const float*)d_in[11];
    const float* W_out  = (const float*)d_in[12];
    const float* b_out  = (const float*)d_in[13];
    const int*   senders   = (const int*)d_in[14];
    const int*   receivers = (const int*)d_in[15];
    const int*   nag       = (const int*)d_in[16];
    float* out = (float*)d_out;

    int n_nodes = in_sizes[0] / 64;
    int n_edges = in_sizes[14];

    uint32_t *pAhi, *pAlo, *pHhi, *pHlo;
    float *pMSG, *pX0, *pX1, *pX2;
    __nv_bfloat16 *pW1h, *pW1l, *pW2h, *pW2l;
    int *pcount;
    cudaGetSymbolAddress((void**)&pAhi,   g_Ahi);
    cudaGetSymbolAddress((void**)&pAlo,   g_Alo);
    cudaGetSymbolAddress((void**)&pHhi,   g_Hhi);
    cudaGetSymbolAddress((void**)&pHlo,   g_Hlo);
    cudaGetSymbolAddress((void**)&pMSG,   g_MSG);
    cudaGetSymbolAddress((void**)&pX0,    g_X0);
    cudaGetSymbolAddress((void**)&pX1,    g_X1);
    cudaGetSymbolAddress((void**)&pX2,    g_X2);
    cudaGetSymbolAddress((void**)&pW1h,   g_W1Thi);
    cudaGetSymbolAddress((void**)&pW1l,   g_W1Tlo);
    cudaGetSymbolAddress((void**)&pW2h,   g_W2Thi);
    cudaGetSymbolAddress((void**)&pW2l,   g_W2Tlo);
    cudaGetSymbolAddress((void**)&pcount, g_count);

    // smem: A 2buf*2plane*128*APAD + B 2buf*2plane*64*APAD, bf16 -> bytes
    const int DSMEM = (2 * 2 * 128 * APAD + 2 * 2 * 64 * APAD) * 2;  // 61440
    auto* g1 = &mma_gemm<160, 256, true>;
    auto* g2 = &mma_gemm<256, 128, false>;
    cudaFuncSetAttribute(g1, cudaFuncAttributeMaxDynamicSharedMemorySize, DSMEM);
    cudaFuncSetAttribute(g2, cudaFuncAttributeMaxDynamicSharedMemorySize, DSMEM);

    const int t = 256;
    prepW_k<<<(160 * 256 + t - 1) / t, t>>>(W_msg1, pW1h, pW1l, 160, 256);
    prepW_k<<<(256 * 128 + t - 1) / t, t>>>(W_msg2, pW2h, pW2l, 256, 128);
    init_k<<<(n_nodes * 128 + t - 1) / t, t>>>(n_nodes);
    compact_k<<<(n_edges + t - 1) / t, t>>>(receivers, nag, n_edges);
    convertA_k<<<((size_t)n_edges * 40 + t - 1) / t, t>>>(node_feats, edge_feats,
                                                          senders, receivers, n_edges);

    int mtiles = (n_edges + 127) / 128;
    mma_gemm<160, 256, true><<<dim3(mtiles, 4), 256, DSMEM>>>(
        (const __nv_bfloat16*)pAhi, (const __nv_bfloat16*)pAlo,
        pW1h, pW1l, b_msg1, pHhi, pHlo, nullptr, pcount);
    mma_gemm<256, 128, false><<<dim3(mtiles, 2), 256, DSMEM>>>(
        (const __nv_bfloat16*)pHhi, (const __nv_bfloat16*)pHlo,
        pW2h, pW2l, b_msg2, nullptr, nullptr, pMSG, pcount);

    logits_k<<<(n_edges * 32 + t - 1) / t, t>>>(w_gate, b_gate);
    aggr_k<<<(n_edges * 32 + t - 1) / t, t>>>();
    norm_k<<<(n_nodes * 128 + t - 1) / t, t>>>(nag, n_nodes);

    dim3 g3((n_nodes + BM - 1) / BM, 2);
    gemm_k<128, 256, true><<<g3, 256>>>(pX0, W_h1, b_h1, pX1, nag);
    gemm_k<256, 256, true><<<g3, 256>>>(pX1, W_h2, b_h2, pX2, nag);
    out_k<<<(n_nodes * 32 + t - 1) / t, t>>>(W_out, b_out, nag, out);
}

// round 14
// speedup vs baseline: 1.3274x; 1.0438x over previous
#include <cuda_runtime.h>
#include <cuda_bf16.h>
#include <cstdint>
#include <cstddef>

// ---------------------------------------------------------------------------
// CBFNet on GB300 (compute_103 — no tcgen05, no cp.async):
//   compact dead edges -> gather+split convert -> bf16 3-term-split HMMA
//   edge MLP -> gated segment softmax (folded norm, vector RED) ->
//   agent MLP also on HMMA (3-term split, same template).
// ---------------------------------------------------------------------------

#define MAXE 800000
#define MAXN 50000

typedef unsigned long long ull;

// Scratch (allocation-free rule: __device__ globals)
__device__ uint32_t g_Ahi[(size_t)MAXE * 80];    // gathered A, bf16x2 hi plane [m][160]
__device__ uint32_t g_Alo[(size_t)MAXE * 80];    // lo plane
__device__ uint32_t g_Hhi[(size_t)MAXE * 128];   // H bf16x2 hi plane [m][256]
__device__ uint32_t g_Hlo[(size_t)MAXE * 128];   // lo plane
__device__ float    g_MSG[(size_t)MAXE * 128];
__device__ float    g_logits[MAXE];
__device__ int      g_eidx[MAXE];
__device__ int      g_rcvc[MAXE];
__device__ unsigned g_segmax[MAXN];
__device__ float    g_denom[MAXN];
__device__ float    g_aggr[(size_t)MAXN * 128];
// Agent activations as bf16x2 planes (+128 rows slack for tile over-launch)
__device__ uint32_t g_X0hi[(size_t)(MAXN + 128) * 64];
__device__ uint32_t g_X0lo[(size_t)(MAXN + 128) * 64];
__device__ uint32_t g_X1hi[(size_t)(MAXN + 128) * 128];
__device__ uint32_t g_X1lo[(size_t)(MAXN + 128) * 128];
__device__ float    g_X2[(size_t)(MAXN + 128) * 256];
__device__ int      g_count[1];

// Transposed bf16 weight planes [N][K] (row.col mma layout: B^T rows k-contig)
__device__ __nv_bfloat16 g_W1Thi[256 * 160];
__device__ __nv_bfloat16 g_W1Tlo[256 * 160];
__device__ __nv_bfloat16 g_W2Thi[128 * 256];
__device__ __nv_bfloat16 g_W2Tlo[128 * 256];
__device__ __nv_bfloat16 g_Wh1Thi[256 * 128];
__device__ __nv_bfloat16 g_Wh1Tlo[256 * 128];
__device__ __nv_bfloat16 g_Wh2Thi[256 * 256];
__device__ __nv_bfloat16 g_Wh2Tlo[256 * 256];

// ============================ helpers ======================================
__device__ __forceinline__ uint32_t smem_u32(const void* p) {
    uint32_t a;
    asm("{ .reg .u64 t; cvta.to.shared.u64 t, %1; cvt.u32.u64 %0, t; }"
        : "=r"(a) : "l"(p));
    return a;
}

// fp32 pair -> packed bf16x2 hi/lo planes
__device__ __forceinline__ void split2(float a, float b, uint32_t& hp, uint32_t& lp) {
    __nv_bfloat16 ha = __float2bfloat16(a), hb = __float2bfloat16(b);
    __nv_bfloat16 la = __float2bfloat16(a - __bfloat162float(ha));
    __nv_bfloat16 lb = __float2bfloat16(b - __bfloat162float(hb));
    hp = ((uint32_t)__bfloat16_as_ushort(hb) << 16) | __bfloat16_as_ushort(ha);
    lp = ((uint32_t)__bfloat16_as_ushort(lb) << 16) | __bfloat16_as_ushort(la);
}

__device__ __forceinline__ void mma16816(float* c, const uint32_t* a, const uint32_t* b) {
    asm volatile(
        "mma.sync.aligned.m16n8k16.row.col.f32.bf16.bf16.f32 "
        "{%0,%1,%2,%3}, {%4,%5,%6,%7}, {%8,%9}, {%0,%1,%2,%3};"
        : "+f"(c[0]), "+f"(c[1]), "+f"(c[2]), "+f"(c[3])
        : "r"(a[0]), "r"(a[1]), "r"(a[2]), "r"(a[3]), "r"(b[0]), "r"(b[1]));
}

#define LDSM_X4(r0, r1, r2, r3, addr) \
    asm volatile("ldmatrix.sync.aligned.m8n8.x4.shared.b16 {%0,%1,%2,%3}, [%4];" \
        : "=r"(r0), "=r"(r1), "=r"(r2), "=r"(r3) : "r"(addr))

// ======================= prep kernels ======================================
__global__ void prepW_k(const float* __restrict__ W,
                        __nv_bfloat16* __restrict__ Thi,
                        __nv_bfloat16* __restrict__ Tlo, int K, int N) {
    int i = blockIdx.x * blockDim.x + threadIdx.x;
    if (i >= K * N) return;
    int n = i / K, k = i % K;
    float v = W[k * N + n];
    __nv_bfloat16 h = __float2bfloat16(v);
    Thi[n * K + k] = h;
    Tlo[n * K + k] = __float2bfloat16(v - __bfloat162float(h));
}

// Gather [sender||receiver||edge] fp32 rows -> packed bf16 hi/lo planes [m][160]
__global__ void convertA_k(const float* __restrict__ nodef,
                           const float* __restrict__ edgef,
                           const int*   __restrict__ senders,
                           const int*   __restrict__ receivers, int n_edges) {
    int i = blockIdx.x * blockDim.x + threadIdx.x;
    int row = i / 40, q = i % 40;
    if (row >= g_count[0]) return;
    int e = g_eidx[row];
    int pos = q * 4;
    const float* src;
    if (pos < 64)       src = nodef + (size_t)senders[e] * 64 + pos;
    else if (pos < 128) src = nodef + (size_t)receivers[e] * 64 + (pos - 64);
    else                src = edgef + (size_t)e * 32 + (pos - 128);
    float4 f = *(const float4*)src;
    uint32_t h0, l0, h1, l1;
    split2(f.x, f.y, h0, l0);
    split2(f.z, f.w, h1, l1);
    size_t o = (size_t)row * 80 + q * 2;
    g_Ahi[o] = h0; g_Ahi[o + 1] = h1;
    g_Alo[o] = l0; g_Alo[o + 1] = l1;
}

// ======================= HMMA 3-term-split GEMM ============================
// C[M, NT] = relu(A @ B + bias); A bf16 hi/lo planes [M][KD] row-major,
// B bf16 hi/lo planes [NT][KD]. CTA 128x64 (grid.y = NT/64), 8 warps 4(M)x2(N),
// warp tile 32x32, BK=32, register-staged double-buffered smem, ldmatrix.x4
// fragment loads, +8 pad. 3 mma passes: hi*hi + hi*lo + lo*hi (fp32 accum).
#define APAD 40   // 32 + 8 pad (bf16 elems per smem row)

template<int KD, int NT, bool SPLIT>
__global__ __launch_bounds__(256, 2)
void mma_gemm(const __nv_bfloat16* __restrict__ Ahi,
              const __nv_bfloat16* __restrict__ Alo,
              const __nv_bfloat16* __restrict__ Bhi,
              const __nv_bfloat16* __restrict__ Blo,
              const float*    __restrict__ bias,
              uint32_t*       __restrict__ Chi,
              uint32_t*       __restrict__ Clo,
              float*          __restrict__ Cf,
              const int*      __restrict__ mptr)
{
    const int M = *mptr;
    const int row0 = blockIdx.x * 128;
    if (row0 >= M) return;
    const int n0  = blockIdx.y * 64;
    const int tid  = threadIdx.x;
    const int lane = tid & 31, wid = tid >> 5;
    const int gq = lane >> 2, tq = lane & 3;
    const int wr = (wid & 3) * 32;      // warp row base (M)
    const int wc = (wid >> 2) * 32;     // warp col base (N, within 64)

    extern __shared__ char dsm[];
    __nv_bfloat16* S = (__nv_bfloat16*)dsm;
    const uint32_t sbase = smem_u32(dsm);
    // bf16-elem layout: A planes [buf*2+p][128][APAD] at 0; B planes at BOFF
    const int BOFF = 2 * 2 * 128 * APAD;   // 20480 elems

    const int fa_r0 = (tid * 2)     >> 2, fa_k0 = ((tid * 2)     & 3) * 8;
    const int fa_r1 = (tid * 2 + 1) >> 2, fa_k1 = ((tid * 2 + 1) & 3) * 8;
    const int fb_r  = tid >> 2,           fb_k  = (tid & 3) * 8;

    uint4 stA[2][2], stB[2];

    auto gload = [&](int kb) {
        #pragma unroll
        for (int p = 0; p < 2; ++p) {
            const __nv_bfloat16* A_ = p ? Alo : Ahi;
            const __nv_bfloat16* B_ = p ? Blo : Bhi;
            stA[p][0] = *(const uint4*)(A_ + (size_t)(row0 + fa_r0) * KD + kb * 32 + fa_k0);
            stA[p][1] = *(const uint4*)(A_ + (size_t)(row0 + fa_r1) * KD + kb * 32 + fa_k1);
            stB[p]    = *(const uint4*)(B_ + (size_t)(n0  + fb_r)  * KD + kb * 32 + fb_k);
        }
    };
    auto sstore = [&](int b) {
        #pragma unroll
        for (int p = 0; p < 2; ++p) {
            *(uint4*)(S + ((b * 2 + p) * 128 + fa_r0) * APAD + fa_k0) = stA[p][0];
            *(uint4*)(S + ((b * 2 + p) * 128 + fa_r1) * APAD + fa_k1) = stA[p][1];
            *(uint4*)(S + BOFF + ((b * 2 + p) * 64 + fb_r) * APAD + fb_k) = stB[p];
        }
    };

    // ldmatrix per-thread address components (bf16-elem offsets)
    const int lm  = lane >> 3, lr = lane & 7;
    const int aRow = wr + (lm & 1) * 8 + lr;   // + mi*16
    const int aCol = (lm >> 1) * 8;            // + kk
    const int bRow = wc + (lm >> 1) * 8 + lr;  // + jblk*16
    const int bCol = (lm & 1) * 8;             // + kk

    float acc[2][4][4];
    #pragma unroll
    for (int mi = 0; mi < 2; ++mi)
        #pragma unroll
        for (int j = 0; j < 4; ++j)
            #pragma unroll
            for (int q = 0; q < 4; ++q) acc[mi][j][q] = 0.f;

    constexpr int NKB = KD / 32;
    int buf = 0;

    gload(0);
    sstore(0);
    __syncthreads();

    #pragma unroll 1
    for (int kb = 0; kb < NKB; ++kb) {
        if (kb + 1 < NKB) gload(kb + 1);

        #pragma unroll
        for (int kk = 0; kk < 32; kk += 16) {
            uint32_t af[2][2][4], bf[2][4][2];
            #pragma unroll
            for (int p = 0; p < 2; ++p) {
                uint32_t ab = sbase + ((buf * 2 + p) * 128 * APAD) * 2;
                #pragma unroll
                for (int mi = 0; mi < 2; ++mi) {
                    uint32_t ad = ab + (((aRow + mi * 16) * APAD) + kk + aCol) * 2;
                    LDSM_X4(af[p][mi][0], af[p][mi][1], af[p][mi][2], af[p][mi][3], ad);
                }
                uint32_t bb = sbase + (BOFF + (buf * 2 + p) * 64 * APAD) * 2;
                #pragma unroll
                for (int jb = 0; jb < 2; ++jb) {
                    uint32_t bd = bb + (((bRow + jb * 16) * APAD) + kk + bCol) * 2;
                    LDSM_X4(bf[p][2 * jb][0], bf[p][2 * jb][1],
                            bf[p][2 * jb + 1][0], bf[p][2 * jb + 1][1], bd);
                }
            }
            #pragma unroll
            for (int mi = 0; mi < 2; ++mi)
                #pragma unroll
                for (int j = 0; j < 4; ++j) {
                    mma16816(acc[mi][j], af[0][mi], bf[0][j]);  // hi*hi
                    mma16816(acc[mi][j], af[0][mi], bf[1][j]);  // hi*lo
                    mma16816(acc[mi][j], af[1][mi], bf[0][j]);  // lo*hi
                }
        }

        if (kb + 1 < NKB) {
            sstore(buf ^ 1);
            __syncthreads();
            buf ^= 1;
        }
    }

    // Epilogue: bias + relu; SPLIT -> bf16 hi/lo planes, else fp32
    #pragma unroll
    for (int mi = 0; mi < 2; ++mi) {
        int r1 = row0 + wr + mi * 16 + gq;
        int r2 = r1 + 8;
        #pragma unroll
        for (int j = 0; j < 4; ++j) {
            int gcol = n0 + wc + j * 8 + tq * 2;
            float2 bv = *(const float2*)(bias + gcol);
            float v0 = fmaxf(acc[mi][j][0] + bv.x, 0.f);
            float v1 = fmaxf(acc[mi][j][1] + bv.y, 0.f);
            float v2 = fmaxf(acc[mi][j][2] + bv.x, 0.f);
            float v3 = fmaxf(acc[mi][j][3] + bv.y, 0.f);
            if (SPLIT) {
                uint32_t hp, lp;
                if (r1 < M) {
                    split2(v0, v1, hp, lp);
                    Chi[(size_t)r1 * (NT / 2) + gcol / 2] = hp;
                    Clo[(size_t)r1 * (NT / 2) + gcol / 2] = lp;
                }
                if (r2 < M) {
                    split2(v2, v3, hp, lp);
                    Chi[(size_t)r2 * (NT / 2) + gcol / 2] = hp;
                    Clo[(size_t)r2 * (NT / 2) + gcol / 2] = lp;
                }
            } else {
                if (r1 < M) *(float2*)(Cf + (size_t)r1 * NT + gcol) = make_float2(v0, v1);
                if (r2 < M) *(float2*)(Cf + (size_t)r2 * NT + gcol) = make_float2(v2, v3);
            }
        }
    }
}

// ======================= small kernels =====================================
__device__ __forceinline__ unsigned fmap(float f) {
    unsigned u = __float_as_uint(f);
    return (u & 0x80000000u) ? ~u : (u | 0x80000000u);
}
__device__ __forceinline__ float funmap(unsigned u) {
    return __uint_as_float((u & 0x80000000u) ? (u ^ 0x80000000u) : ~u);
}

__global__ void init_k(int n_nodes) {
    int i = blockIdx.x * blockDim.x + threadIdx.x;
    if (i < n_nodes * 128) g_aggr[i] = 0.f;
    if (i < n_nodes) { g_denom[i] = 0.f; g_segmax[i] = 0u; }
    if (i == 0) g_count[0] = 0;
}

// Warp-aggregated compaction of edges with receiver < n_agents.
__global__ void compact_k(const int* __restrict__ receivers,
                          const int* __restrict__ nag, int n_edges) {
    int e = blockIdx.x * blockDim.x + threadIdx.x;
    int lane = threadIdx.x & 31;
    int r = (e < n_edges) ? receivers[e] : 0x7fffffff;
    bool act = (e < n_edges) && (r < *nag);
    unsigned m = __ballot_sync(0xffffffffu, act);
    if (!m) return;
    int leader = __ffs(m) - 1;
    int base = 0;
    if (lane == leader) base = atomicAdd(g_count, __popc(m));
    base = __shfl_sync(0xffffffffu, base, leader);
    if (act) {
        int pos = base + __popc(m & ((1u << lane) - 1u));
        g_eidx[pos] = e;
        g_rcvc[pos] = r;
    }
}

__global__ void logits_k(const float* __restrict__ w_gate,
                         const float* __restrict__ b_gate) {
    int idx  = blockIdx.x * blockDim.x + threadIdx.x;
    int row  = idx >> 5, lane = idx & 31;
    if (row >= g_count[0]) return;
    float4 m4 = *(const float4*)(g_MSG + (size_t)row * 128 + lane * 4);
    float4 g4 = *(const float4*)(w_gate + lane * 4);
    float s = m4.x * g4.x + m4.y * g4.y + m4.z * g4.z + m4.w * g4.w;
    #pragma unroll
    for (int o = 16; o; o >>= 1) s += __shfl_xor_sync(0xffffffffu, s, o);
    if (lane == 0) {
        float lg = s + b_gate[0];
        g_logits[row] = lg;
        atomicMax(&g_segmax[g_rcvc[row]], fmap(lg));
    }
}

__global__ void aggr_k() {
    int idx = blockIdx.x * blockDim.x + threadIdx.x;
    int row = idx >> 5, lane = idx & 31;
    if (row >= g_count[0]) return;
    int rv = g_rcvc[row];
    float w = expf(g_logits[row] - funmap(g_segmax[rv]));
    if (lane == 0) atomicAdd(&g_denom[rv], w);
    float4 m4 = *(const float4*)(g_MSG + (size_t)row * 128 + lane * 4);
    float* dst = g_aggr + (size_t)rv * 128 + lane * 4;
    asm volatile("red.global.add.v4.f32 [%0], {%1, %2, %3, %4};"
                 :: "l"(dst), "f"(m4.x * w), "f"(m4.y * w),
                    "f"(m4.z * w), "f"(m4.w * w)
                 : "memory");
}

// Normalize aggr by denom and emit X0 as bf16 hi/lo planes.
__global__ void norm_k(const int* __restrict__ nag, int n_nodes) {
    int i = blockIdx.x * blockDim.x + threadIdx.x;
    if (i >= n_nodes * 64) return;
    int row = i >> 6, c = i & 63;
    if (row >= *nag) return;
    float d = g_denom[row] + 1e-9f;
    float a = g_aggr[(size_t)row * 128 + 2 * c]     / d;
    float b = g_aggr[(size_t)row * 128 + 2 * c + 1] / d;
    uint32_t hp, lp;
    split2(a, b, hp, lp);
    g_X0hi[(size_t)row * 64 + c] = hp;
    g_X0lo[(size_t)row * 64 + c] = lp;
}

__global__ void out_k(const float* __restrict__ W, const float* __restrict__ b,
                      const int* __restrict__ nag, float* __restrict__ out) {
    int idx = blockIdx.x * blockDim.x + threadIdx.x;
    int row = idx >> 5, lane = idx & 31;
    if (row >= *nag) return;
    const float4* xr = (const float4*)(g_X2 + (size_t)row * 256);
    const float4* wr = (const float4*)W;
    float s = 0.f;
    #pragma unroll
    for (int j = 0; j < 2; ++j) {
        float4 x = xr[lane + 32 * j], wv = wr[lane + 32 * j];
        s += x.x * wv.x + x.y * wv.y + x.z * wv.z + x.w * wv.w;
    }
    #pragma unroll
    for (int o = 16; o; o >>= 1) s += __shfl_xor_sync(0xffffffffu, s, o);
    if (lane == 0) out[row] = tanhf(s + b[0]);
}

// ---------------------------------------------------------------------------
extern "C" void kernel_launch(void* const* d_in, const int* in_sizes, int n_in,
                              void* d_out, int out_size)
{
    const float* node_feats = (const float*)d_in[0];
    const float* edge_feats = (const float*)d_in[1];
    const float* W_msg1 = (const float*)d_in[2];
    const float* b_msg1 = (const float*)d_in[3];
    const float* W_msg2 = (const float*)d_in[4];
    const float* b_msg2 = (const float*)d_in[5];
    const float* w_gate = (const float*)d_in[6];
    const float* b_gate = (const float*)d_in[7];
    const float* W_h1   = (const float*)d_in[8];
    const float* b_h1   = (const float*)d_in[9];
    const float* W_h2   = (const float*)d_in[10];
    const float* b_h2   = (const float*)d_in[11];
    const float* W_out  = (const float*)d_in[12];
    const float* b_out  = (const float*)d_in[13];
    const int*   senders   = (const int*)d_in[14];
    const int*   receivers = (const int*)d_in[15];
    const int*   nag       = (const int*)d_in[16];
    float* out = (float*)d_out;

    int n_nodes = in_sizes[0] / 64;
    int n_edges = in_sizes[14];

    uint32_t *pAhi, *pAlo, *pHhi, *pHlo, *pX0hi, *pX0lo, *pX1hi, *pX1lo;
    float *pMSG, *pX2;
    __nv_bfloat16 *pW1h, *pW1l, *pW2h, *pW2l, *pWh1h, *pWh1l, *pWh2h, *pWh2l;
    int *pcount;
    cudaGetSymbolAddress((void**)&pAhi,   g_Ahi);
    cudaGetSymbolAddress((void**)&pAlo,   g_Alo);
    cudaGetSymbolAddress((void**)&pHhi,   g_Hhi);
    cudaGetSymbolAddress((void**)&pHlo,   g_Hlo);
    cudaGetSymbolAddress((void**)&pMSG,   g_MSG);
    cudaGetSymbolAddress((void**)&pX0hi,  g_X0hi);
    cudaGetSymbolAddress((void**)&pX0lo,  g_X0lo);
    cudaGetSymbolAddress((void**)&pX1hi,  g_X1hi);
    cudaGetSymbolAddress((void**)&pX1lo,  g_X1lo);
    cudaGetSymbolAddress((void**)&pX2,    g_X2);
    cudaGetSymbolAddress((void**)&pW1h,   g_W1Thi);
    cudaGetSymbolAddress((void**)&pW1l,   g_W1Tlo);
    cudaGetSymbolAddress((void**)&pW2h,   g_W2Thi);
    cudaGetSymbolAddress((void**)&pW2l,   g_W2Tlo);
    cudaGetSymbolAddress((void**)&pWh1h,  g_Wh1Thi);
    cudaGetSymbolAddress((void**)&pWh1l,  g_Wh1Tlo);
    cudaGetSymbolAddress((void**)&pWh2h,  g_Wh2Thi);
    cudaGetSymbolAddress((void**)&pWh2l,  g_Wh2Tlo);
    cudaGetSymbolAddress((void**)&pcount, g_count);

    // smem: A 2buf*2plane*128*APAD + B 2buf*2plane*64*APAD, bf16 -> bytes
    const int DSMEM = (2 * 2 * 128 * APAD + 2 * 2 * 64 * APAD) * 2;  // 61440
    auto* g1 = &mma_gemm<160, 256, true>;
    auto* g2 = &mma_gemm<256, 128, false>;
    auto* g3 = &mma_gemm<128, 256, true>;
    auto* g4 = &mma_gemm<256, 256, false>;
    cudaFuncSetAttribute(g1, cudaFuncAttributeMaxDynamicSharedMemorySize, DSMEM);
    cudaFuncSetAttribute(g2, cudaFuncAttributeMaxDynamicSharedMemorySize, DSMEM);
    cudaFuncSetAttribute(g3, cudaFuncAttributeMaxDynamicSharedMemorySize, DSMEM);
    cudaFuncSetAttribute(g4, cudaFuncAttributeMaxDynamicSharedMemorySize, DSMEM);

    const int t = 256;
    prepW_k<<<(160 * 256 + t - 1) / t, t>>>(W_msg1, pW1h, pW1l, 160, 256);
    prepW_k<<<(256 * 128 + t - 1) / t, t>>>(W_msg2, pW2h, pW2l, 256, 128);
    prepW_k<<<(128 * 256 + t - 1) / t, t>>>(W_h1, pWh1h, pWh1l, 128, 256);
    prepW_k<<<(256 * 256 + t - 1) / t, t>>>(W_h2, pWh2h, pWh2l, 256, 256);
    init_k<<<(n_nodes * 128 + t - 1) / t, t>>>(n_nodes);
    compact_k<<<(n_edges + t - 1) / t, t>>>(receivers, nag, n_edges);
    convertA_k<<<((size_t)n_edges * 40 + t - 1) / t, t>>>(node_feats, edge_feats,
                                                          senders, receivers, n_edges);

    // Edge MLP (M = compacted count, read on device)
    int mtiles = (n_edges + 127) / 128;
    mma_gemm<160, 256, true><<<dim3(mtiles, 4), 256, DSMEM>>>(
        (const __nv_bfloat16*)pAhi, (const __nv_bfloat16*)pAlo,
        pW1h, pW1l, b_msg1, pHhi, pHlo, nullptr, pcount);
    mma_gemm<256, 128, false><<<dim3(mtiles, 2), 256, DSMEM>>>(
        (const __nv_bfloat16*)pHhi, (const __nv_bfloat16*)pHlo,
        pW2h, pW2l, b_msg2, nullptr, nullptr, pMSG, pcount);

    // Gated segment softmax aggregation
    logits_k<<<(n_edges * 32 + t - 1) / t, t>>>(w_gate, b_gate);
    aggr_k<<<(n_edges * 32 + t - 1) / t, t>>>();
    norm_k<<<(n_nodes * 64 + t - 1) / t, t>>>(nag, n_nodes);

    // Agent MLP on HMMA (M = n_agents, read on device; tiles over-launched)
    int mtilesA = (n_nodes + 127) / 128;
    mma_gemm<128, 256, true><<<dim3(mtilesA, 4), 256, DSMEM>>>(
        (const __nv_bfloat16*)pX0hi, (const __nv_bfloat16*)pX0lo,
        pWh1h, pWh1l, b_h1, pX1hi, pX1lo, nullptr, nag);
    mma_gemm<256, 256, false><<<dim3(mtilesA, 4), 256, DSMEM>>>(
        (const __nv_bfloat16*)pX1hi, (const __nv_bfloat16*)pX1lo,
        pWh2h, pWh2l, b_h2, nullptr, nullptr, pX2, nag);
    out_k<<<(n_nodes * 32 + t - 1) / t, t>>>(W_out, b_out, nag, out);
}

// round 15
// speedup vs baseline: 1.3683x; 1.0308x over previous
#include <cuda_runtime.h>
#include <cuda_bf16.h>
#include <cstdint>
#include <cstddef>

// ---------------------------------------------------------------------------
// CBFNet on GB300 (compute_103 — no tcgen05, no cp.async):
//   compact dead edges -> gather+split convert -> bf16 3-term-split HMMA
//   edge MLP -> gated segment softmax (folded norm, vector RED) ->
//   agent MLP also on HMMA. Grid: x = n-tile, y = row-tile so CTAs sharing
//   A rows are L2-co-resident (kills 4x/2x DRAM re-reads of activations).
// ---------------------------------------------------------------------------

#define MAXE 800000
#define MAXN 50000

typedef unsigned long long ull;

// Scratch (allocation-free rule: __device__ globals)
__device__ uint32_t g_Ahi[(size_t)MAXE * 80];    // gathered A, bf16x2 hi plane [m][160]
__device__ uint32_t g_Alo[(size_t)MAXE * 80];    // lo plane
__device__ uint32_t g_Hhi[(size_t)MAXE * 128];   // H bf16x2 hi plane [m][256]
__device__ uint32_t g_Hlo[(size_t)MAXE * 128];   // lo plane
__device__ float    g_MSG[(size_t)MAXE * 128];
__device__ float    g_logits[MAXE];
__device__ int      g_eidx[MAXE];
__device__ int      g_rcvc[MAXE];
__device__ unsigned g_segmax[MAXN];
__device__ float    g_denom[MAXN];
__device__ float    g_aggr[(size_t)MAXN * 128];
// Agent activations as bf16x2 planes (+128 rows slack for tile over-launch)
__device__ uint32_t g_X0hi[(size_t)(MAXN + 128) * 64];
__device__ uint32_t g_X0lo[(size_t)(MAXN + 128) * 64];
__device__ uint32_t g_X1hi[(size_t)(MAXN + 128) * 128];
__device__ uint32_t g_X1lo[(size_t)(MAXN + 128) * 128];
__device__ float    g_X2[(size_t)(MAXN + 128) * 256];
__device__ int      g_count[1];

// Transposed bf16 weight planes [N][K] (row.col mma layout: B^T rows k-contig)
__device__ __nv_bfloat16 g_W1Thi[256 * 160];
__device__ __nv_bfloat16 g_W1Tlo[256 * 160];
__device__ __nv_bfloat16 g_W2Thi[128 * 256];
__device__ __nv_bfloat16 g_W2Tlo[128 * 256];
__device__ __nv_bfloat16 g_Wh1Thi[256 * 128];
__device__ __nv_bfloat16 g_Wh1Tlo[256 * 128];
__device__ __nv_bfloat16 g_Wh2Thi[256 * 256];
__device__ __nv_bfloat16 g_Wh2Tlo[256 * 256];

// ============================ helpers ======================================
__device__ __forceinline__ uint32_t smem_u32(const void* p) {
    uint32_t a;
    asm("{ .reg .u64 t; cvta.to.shared.u64 t, %1; cvt.u32.u64 %0, t; }"
        : "=r"(a) : "l"(p));
    return a;
}

// fp32 pair -> packed bf16x2 hi/lo planes
__device__ __forceinline__ void split2(float a, float b, uint32_t& hp, uint32_t& lp) {
    __nv_bfloat16 ha = __float2bfloat16(a), hb = __float2bfloat16(b);
    __nv_bfloat16 la = __float2bfloat16(a - __bfloat162float(ha));
    __nv_bfloat16 lb = __float2bfloat16(b - __bfloat162float(hb));
    hp = ((uint32_t)__bfloat16_as_ushort(hb) << 16) | __bfloat16_as_ushort(ha);
    lp = ((uint32_t)__bfloat16_as_ushort(lb) << 16) | __bfloat16_as_ushort(la);
}

__device__ __forceinline__ void mma16816(float* c, const uint32_t* a, const uint32_t* b) {
    asm volatile(
        "mma.sync.aligned.m16n8k16.row.col.f32.bf16.bf16.f32 "
        "{%0,%1,%2,%3}, {%4,%5,%6,%7}, {%8,%9}, {%0,%1,%2,%3};"
        : "+f"(c[0]), "+f"(c[1]), "+f"(c[2]), "+f"(c[3])
        : "r"(a[0]), "r"(a[1]), "r"(a[2]), "r"(a[3]), "r"(b[0]), "r"(b[1]));
}

#define LDSM_X4(r0, r1, r2, r3, addr) \
    asm volatile("ldmatrix.sync.aligned.m8n8.x4.shared.b16 {%0,%1,%2,%3}, [%4];" \
        : "=r"(r0), "=r"(r1), "=r"(r2), "=r"(r3) : "r"(addr))

// ======================= prep kernels ======================================
__global__ void prepW_k(const float* __restrict__ W,
                        __nv_bfloat16* __restrict__ Thi,
                        __nv_bfloat16* __restrict__ Tlo, int K, int N) {
    int i = blockIdx.x * blockDim.x + threadIdx.x;
    if (i >= K * N) return;
    int n = i / K, k = i % K;
    float v = W[k * N + n];
    __nv_bfloat16 h = __float2bfloat16(v);
    Thi[n * K + k] = h;
    Tlo[n * K + k] = __float2bfloat16(v - __bfloat162float(h));
}

// Gather [sender||receiver||edge] fp32 rows -> packed bf16 hi/lo planes [m][160]
__global__ void convertA_k(const float* __restrict__ nodef,
                           const float* __restrict__ edgef,
                           const int*   __restrict__ senders,
                           const int*   __restrict__ receivers, int n_edges) {
    int i = blockIdx.x * blockDim.x + threadIdx.x;
    int row = i / 40, q = i % 40;
    if (row >= g_count[0]) return;
    int e = g_eidx[row];
    int pos = q * 4;
    const float* src;
    if (pos < 64)       src = nodef + (size_t)senders[e] * 64 + pos;
    else if (pos < 128) src = nodef + (size_t)receivers[e] * 64 + (pos - 64);
    else                src = edgef + (size_t)e * 32 + (pos - 128);
    float4 f = *(const float4*)src;
    uint32_t h0, l0, h1, l1;
    split2(f.x, f.y, h0, l0);
    split2(f.z, f.w, h1, l1);
    size_t o = (size_t)row * 80 + q * 2;
    g_Ahi[o] = h0; g_Ahi[o + 1] = h1;
    g_Alo[o] = l0; g_Alo[o + 1] = l1;
}

// ======================= HMMA 3-term-split GEMM ============================
// C[M, NT] = relu(A @ B + bias); A bf16 hi/lo planes [M][KD] row-major,
// B bf16 hi/lo planes [NT][KD]. CTA 128x64. Grid: x = n-tile (NT/64),
// y = row-tile — CTAs sharing the same A rows are ADJACENT so A is read once
// from DRAM and the rest hits L2. 8 warps 4(M)x2(N), warp tile 32x32, BK=32,
// register-staged double-buffered smem, ldmatrix.x4 frags, +8 pad.
// 3 mma passes: hi*hi + hi*lo + lo*hi (fp32 accum).
#define APAD 40   // 32 + 8 pad (bf16 elems per smem row)

template<int KD, int NT, bool SPLIT>
__global__ __launch_bounds__(256, 2)
void mma_gemm(const __nv_bfloat16* __restrict__ Ahi,
              const __nv_bfloat16* __restrict__ Alo,
              const __nv_bfloat16* __restrict__ Bhi,
              const __nv_bfloat16* __restrict__ Blo,
              const float*    __restrict__ bias,
              uint32_t*       __restrict__ Chi,
              uint32_t*       __restrict__ Clo,
              float*          __restrict__ Cf,
              const int*      __restrict__ mptr)
{
    const int M = *mptr;
    const int row0 = blockIdx.y * 128;        // row-tile on Y (grid-swap)
    if (row0 >= M) return;
    const int n0  = blockIdx.x * 64;          // n-tile on X (adjacent ids share A)
    const int tid  = threadIdx.x;
    const int lane = tid & 31, wid = tid >> 5;
    const int gq = lane >> 2, tq = lane & 3;
    const int wr = (wid & 3) * 32;      // warp row base (M)
    const int wc = (wid >> 2) * 32;     // warp col base (N, within 64)

    extern __shared__ char dsm[];
    __nv_bfloat16* S = (__nv_bfloat16*)dsm;
    const uint32_t sbase = smem_u32(dsm);
    // bf16-elem layout: A planes [buf*2+p][128][APAD] at 0; B planes at BOFF
    const int BOFF = 2 * 2 * 128 * APAD;   // 20480 elems

    const int fa_r0 = (tid * 2)     >> 2, fa_k0 = ((tid * 2)     & 3) * 8;
    const int fa_r1 = (tid * 2 + 1) >> 2, fa_k1 = ((tid * 2 + 1) & 3) * 8;
    const int fb_r  = tid >> 2,           fb_k  = (tid & 3) * 8;

    uint4 stA[2][2], stB[2];

    auto gload = [&](int kb) {
        #pragma unroll
        for (int p = 0; p < 2; ++p) {
            const __nv_bfloat16* A_ = p ? Alo : Ahi;
            const __nv_bfloat16* B_ = p ? Blo : Bhi;
            stA[p][0] = *(const uint4*)(A_ + (size_t)(row0 + fa_r0) * KD + kb * 32 + fa_k0);
            stA[p][1] = *(const uint4*)(A_ + (size_t)(row0 + fa_r1) * KD + kb * 32 + fa_k1);
            stB[p]    = *(const uint4*)(B_ + (size_t)(n0  + fb_r)  * KD + kb * 32 + fb_k);
        }
    };
    auto sstore = [&](int b) {
        #pragma unroll
        for (int p = 0; p < 2; ++p) {
            *(uint4*)(S + ((b * 2 + p) * 128 + fa_r0) * APAD + fa_k0) = stA[p][0];
            *(uint4*)(S + ((b * 2 + p) * 128 + fa_r1) * APAD + fa_k1) = stA[p][1];
            *(uint4*)(S + BOFF + ((b * 2 + p) * 64 + fb_r) * APAD + fb_k) = stB[p];
        }
    };

    // ldmatrix per-thread address components (bf16-elem offsets)
    const int lm  = lane >> 3, lr = lane & 7;
    const int aRow = wr + (lm & 1) * 8 + lr;   // + mi*16
    const int aCol = (lm >> 1) * 8;            // + kk
    const int bRow = wc + (lm >> 1) * 8 + lr;  // + jblk*16
    const int bCol = (lm & 1) * 8;             // + kk

    float acc[2][4][4];
    #pragma unroll
    for (int mi = 0; mi < 2; ++mi)
        #pragma unroll
        for (int j = 0; j < 4; ++j)
            #pragma unroll
            for (int q = 0; q < 4; ++q) acc[mi][j][q] = 0.f;

    constexpr int NKB = KD / 32;
    int buf = 0;

    gload(0);
    sstore(0);
    __syncthreads();

    #pragma unroll 1
    for (int kb = 0; kb < NKB; ++kb) {
        if (kb + 1 < NKB) gload(kb + 1);

        #pragma unroll
        for (int kk = 0; kk < 32; kk += 16) {
            uint32_t af[2][2][4], bf[2][4][2];
            #pragma unroll
            for (int p = 0; p < 2; ++p) {
                uint32_t ab = sbase + ((buf * 2 + p) * 128 * APAD) * 2;
                #pragma unroll
                for (int mi = 0; mi < 2; ++mi) {
                    uint32_t ad = ab + (((aRow + mi * 16) * APAD) + kk + aCol) * 2;
                    LDSM_X4(af[p][mi][0], af[p][mi][1], af[p][mi][2], af[p][mi][3], ad);
                }
                uint32_t bb = sbase + (BOFF + (buf * 2 + p) * 64 * APAD) * 2;
                #pragma unroll
                for (int jb = 0; jb < 2; ++jb) {
                    uint32_t bd = bb + (((bRow + jb * 16) * APAD) + kk + bCol) * 2;
                    LDSM_X4(bf[p][2 * jb][0], bf[p][2 * jb][1],
                            bf[p][2 * jb + 1][0], bf[p][2 * jb + 1][1], bd);
                }
            }
            #pragma unroll
            for (int mi = 0; mi < 2; ++mi)
                #pragma unroll
                for (int j = 0; j < 4; ++j) {
                    mma16816(acc[mi][j], af[0][mi], bf[0][j]);  // hi*hi
                    mma16816(acc[mi][j], af[0][mi], bf[1][j]);  // hi*lo
                    mma16816(acc[mi][j], af[1][mi], bf[0][j]);  // lo*hi
                }
        }

        if (kb + 1 < NKB) {
            sstore(buf ^ 1);
            __syncthreads();
            buf ^= 1;
        }
    }

    // Epilogue: bias + relu; SPLIT -> bf16 hi/lo planes, else fp32
    #pragma unroll
    for (int mi = 0; mi < 2; ++mi) {
        int r1 = row0 + wr + mi * 16 + gq;
        int r2 = r1 + 8;
        #pragma unroll
        for (int j = 0; j < 4; ++j) {
            int gcol = n0 + wc + j * 8 + tq * 2;
            float2 bv = *(const float2*)(bias + gcol);
            float v0 = fmaxf(acc[mi][j][0] + bv.x, 0.f);
            float v1 = fmaxf(acc[mi][j][1] + bv.y, 0.f);
            float v2 = fmaxf(acc[mi][j][2] + bv.x, 0.f);
            float v3 = fmaxf(acc[mi][j][3] + bv.y, 0.f);
            if (SPLIT) {
                uint32_t hp, lp;
                if (r1 < M) {
                    split2(v0, v1, hp, lp);
                    Chi[(size_t)r1 * (NT / 2) + gcol / 2] = hp;
                    Clo[(size_t)r1 * (NT / 2) + gcol / 2] = lp;
                }
                if (r2 < M) {
                    split2(v2, v3, hp, lp);
                    Chi[(size_t)r2 * (NT / 2) + gcol / 2] = hp;
                    Clo[(size_t)r2 * (NT / 2) + gcol / 2] = lp;
                }
            } else {
                if (r1 < M) *(float2*)(Cf + (size_t)r1 * NT + gcol) = make_float2(v0, v1);
                if (r2 < M) *(float2*)(Cf + (size_t)r2 * NT + gcol) = make_float2(v2, v3);
            }
        }
    }
}

// ======================= small kernels =====================================
__device__ __forceinline__ unsigned fmap(float f) {
    unsigned u = __float_as_uint(f);
    return (u & 0x80000000u) ? ~u : (u | 0x80000000u);
}
__device__ __forceinline__ float funmap(unsigned u) {
    return __uint_as_float((u & 0x80000000u) ? (u ^ 0x80000000u) : ~u);
}

__global__ void init_k(int n_nodes) {
    int i = blockIdx.x * blockDim.x + threadIdx.x;
    if (i < n_nodes * 128) g_aggr[i] = 0.f;
    if (i < n_nodes) { g_denom[i] = 0.f; g_segmax[i] = 0u; }
    if (i == 0) g_count[0] = 0;
}

// Warp-aggregated compaction of edges with receiver < n_agents.
__global__ void compact_k(const int* __restrict__ receivers,
                          const int* __restrict__ nag, int n_edges) {
    int e = blockIdx.x * blockDim.x + threadIdx.x;
    int lane = threadIdx.x & 31;
    int r = (e < n_edges) ? receivers[e] : 0x7fffffff;
    bool act = (e < n_edges) && (r < *nag);
    unsigned m = __ballot_sync(0xffffffffu, act);
    if (!m) return;
    int leader = __ffs(m) - 1;
    int base = 0;
    if (lane == leader) base = atomicAdd(g_count, __popc(m));
    base = __shfl_sync(0xffffffffu, base, leader);
    if (act) {
        int pos = base + __popc(m & ((1u << lane) - 1u));
        g_eidx[pos] = e;
        g_rcvc[pos] = r;
    }
}

__global__ void logits_k(const float* __restrict__ w_gate,
                         const float* __restrict__ b_gate) {
    int idx  = blockIdx.x * blockDim.x + threadIdx.x;
    int row  = idx >> 5, lane = idx & 31;
    if (row >= g_count[0]) return;
    float4 m4 = *(const float4*)(g_MSG + (size_t)row * 128 + lane * 4);
    float4 g4 = *(const float4*)(w_gate + lane * 4);
    float s = m4.x * g4.x + m4.y * g4.y + m4.z * g4.z + m4.w * g4.w;
    #pragma unroll
    for (int o = 16; o; o >>= 1) s += __shfl_xor_sync(0xffffffffu, s, o);
    if (lane == 0) {
        float lg = s + b_gate[0];
        g_logits[row] = lg;
        atomicMax(&g_segmax[g_rcvc[row]], fmap(lg));
    }
}

__global__ void aggr_k() {
    int idx = blockIdx.x * blockDim.x + threadIdx.x;
    int row = idx >> 5, lane = idx & 31;
    if (row >= g_count[0]) return;
    int rv = g_rcvc[row];
    float w = expf(g_logits[row] - funmap(g_segmax[rv]));
    if (lane == 0) atomicAdd(&g_denom[rv], w);
    float4 m4 = *(const float4*)(g_MSG + (size_t)row * 128 + lane * 4);
    float* dst = g_aggr + (size_t)rv * 128 + lane * 4;
    asm volatile("red.global.add.v4.f32 [%0], {%1, %2, %3, %4};"
                 :: "l"(dst), "f"(m4.x * w), "f"(m4.y * w),
                    "f"(m4.z * w), "f"(m4.w * w)
                 : "memory");
}

// Normalize aggr by denom and emit X0 as bf16 hi/lo planes.
__global__ void norm_k(const int* __restrict__ nag, int n_nodes) {
    int i = blockIdx.x * blockDim.x + threadIdx.x;
    if (i >= n_nodes * 64) return;
    int row = i >> 6, c = i & 63;
    if (row >= *nag) return;
    float d = g_denom[row] + 1e-9f;
    float a = g_aggr[(size_t)row * 128 + 2 * c]     / d;
    float b = g_aggr[(size_t)row * 128 + 2 * c + 1] / d;
    uint32_t hp, lp;
    split2(a, b, hp, lp);
    g_X0hi[(size_t)row * 64 + c] = hp;
    g_X0lo[(size_t)row * 64 + c] = lp;
}

__global__ void out_k(const float* __restrict__ W, const float* __restrict__ b,
                      const int* __restrict__ nag, float* __restrict__ out) {
    int idx = blockIdx.x * blockDim.x + threadIdx.x;
    int row = idx >> 5, lane = idx & 31;
    if (row >= *nag) return;
    const float4* xr = (const float4*)(g_X2 + (size_t)row * 256);
    const float4* wr = (const float4*)W;
    float s = 0.f;
    #pragma unroll
    for (int j = 0; j < 2; ++j) {
        float4 x = xr[lane + 32 * j], wv = wr[lane + 32 * j];
        s += x.x * wv.x + x.y * wv.y + x.z * wv.z + x.w * wv.w;
    }
    #pragma unroll
    for (int o = 16; o; o >>= 1) s += __shfl_xor_sync(0xffffffffu, s, o);
    if (lane == 0) out[row] = tanhf(s + b[0]);
}

// ---------------------------------------------------------------------------
extern "C" void kernel_launch(void* const* d_in, const int* in_sizes, int n_in,
                              void* d_out, int out_size)
{
    const float* node_feats = (const float*)d_in[0];
    const float* edge_feats = (const float*)d_in[1];
    const float* W_msg1 = (const float*)d_in[2];
    const float* b_msg1 = (const float*)d_in[3];
    const float* W_msg2 = (const float*)d_in[4];
    const float* b_msg2 = (const float*)d_in[5];
    const float* w_gate = (const float*)d_in[6];
    const float* b_gate = (const float*)d_in[7];
    const float* W_h1   = (const float*)d_in[8];
    const float* b_h1   = (const float*)d_in[9];
    const float* W_h2   = (const float*)d_in[10];
    const float* b_h2   = (const float*)d_in[11];
    const float* W_out  = (const float*)d_in[12];
    const float* b_out  = (const float*)d_in[13];
    const int*   senders   = (const int*)d_in[14];
    const int*   receivers = (const int*)d_in[15];
    const int*   nag       = (const int*)d_in[16];
    float* out = (float*)d_out;

    int n_nodes = in_sizes[0] / 64;
    int n_edges = in_sizes[14];

    uint32_t *pAhi, *pAlo, *pHhi, *pHlo, *pX0hi, *pX0lo, *pX1hi, *pX1lo;
    float *pMSG, *pX2;
    __nv_bfloat16 *pW1h, *pW1l, *pW2h, *pW2l, *pWh1h, *pWh1l, *pWh2h, *pWh2l;
    int *pcount;
    cudaGetSymbolAddress((void**)&pAhi,   g_Ahi);
    cudaGetSymbolAddress((void**)&pAlo,   g_Alo);
    cudaGetSymbolAddress((void**)&pHhi,   g_Hhi);
    cudaGetSymbolAddress((void**)&pHlo,   g_Hlo);
    cudaGetSymbolAddress((void**)&pMSG,   g_MSG);
    cudaGetSymbolAddress((void**)&pX0hi,  g_X0hi);
    cudaGetSymbolAddress((void**)&pX0lo,  g_X0lo);
    cudaGetSymbolAddress((void**)&pX1hi,  g_X1hi);
    cudaGetSymbolAddress((void**)&pX1lo,  g_X1lo);
    cudaGetSymbolAddress((void**)&pX2,    g_X2);
    cudaGetSymbolAddress((void**)&pW1h,   g_W1Thi);
    cudaGetSymbolAddress((void**)&pW1l,   g_W1Tlo);
    cudaGetSymbolAddress((void**)&pW2h,   g_W2Thi);
    cudaGetSymbolAddress((void**)&pW2l,   g_W2Tlo);
    cudaGetSymbolAddress((void**)&pWh1h,  g_Wh1Thi);
    cudaGetSymbolAddress((void**)&pWh1l,  g_Wh1Tlo);
    cudaGetSymbolAddress((void**)&pWh2h,  g_Wh2Thi);
    cudaGetSymbolAddress((void**)&pWh2l,  g_Wh2Tlo);
    cudaGetSymbolAddress((void**)&pcount, g_count);

    // smem: A 2buf*2plane*128*APAD + B 2buf*2plane*64*APAD, bf16 -> bytes
    const int DSMEM = (2 * 2 * 128 * APAD + 2 * 2 * 64 * APAD) * 2;  // 61440
    auto* g1 = &mma_gemm<160, 256, true>;
    auto* g2 = &mma_gemm<256, 128, false>;
    auto* g3 = &mma_gemm<128, 256, true>;
    auto* g4 = &mma_gemm<256, 256, false>;
    cudaFuncSetAttribute(g1, cudaFuncAttributeMaxDynamicSharedMemorySize, DSMEM);
    cudaFuncSetAttribute(g2, cudaFuncAttributeMaxDynamicSharedMemorySize, DSMEM);
    cudaFuncSetAttribute(g3, cudaFuncAttributeMaxDynamicSharedMemorySize, DSMEM);
    cudaFuncSetAttribute(g4, cudaFuncAttributeMaxDynamicSharedMemorySize, DSMEM);

    const int t = 256;
    prepW_k<<<(160 * 256 + t - 1) / t, t>>>(W_msg1, pW1h, pW1l, 160, 256);
    prepW_k<<<(256 * 128 + t - 1) / t, t>>>(W_msg2, pW2h, pW2l, 256, 128);
    prepW_k<<<(128 * 256 + t - 1) / t, t>>>(W_h1, pWh1h, pWh1l, 128, 256);
    prepW_k<<<(256 * 256 + t - 1) / t, t>>>(W_h2, pWh2h, pWh2l, 256, 256);
    init_k<<<(n_nodes * 128 + t - 1) / t, t>>>(n_nodes);
    compact_k<<<(n_edges + t - 1) / t, t>>>(receivers, nag, n_edges);
    convertA_k<<<((size_t)n_edges * 40 + t - 1) / t, t>>>(node_feats, edge_feats,
                                                          senders, receivers, n_edges);

    // Edge MLP (M = compacted count, read on device). Grid: (n-tiles, row-tiles).
    int mtiles = (n_edges + 127) / 128;
    mma_gemm<160, 256, true><<<dim3(4, mtiles), 256, DSMEM>>>(
        (const __nv_bfloat16*)pAhi, (const __nv_bfloat16*)pAlo,
        pW1h, pW1l, b_msg1, pHhi, pHlo, nullptr, pcount);
    mma_gemm<256, 128, false><<<dim3(2, mtiles), 256, DSMEM>>>(
        (const __nv_bfloat16*)pHhi, (const __nv_bfloat16*)pHlo,
        pW2h, pW2l, b_msg2, nullptr, nullptr, pMSG, pcount);

    // Gated segment softmax aggregation
    logits_k<<<(n_edges * 32 + t - 1) / t, t>>>(w_gate, b_gate);
    aggr_k<<<(n_edges * 32 + t - 1) / t, t>>>();
    norm_k<<<(n_nodes * 64 + t - 1) / t, t>>>(nag, n_nodes);

    // Agent MLP on HMMA (M = n_agents, read on device; tiles over-launched)
    int mtilesA = (n_nodes + 127) / 128;
    mma_gemm<128, 256, true><<<dim3(4, mtilesA), 256, DSMEM>>>(
        (const __nv_bfloat16*)pX0hi, (const __nv_bfloat16*)pX0lo,
        pWh1h, pWh1l, b_h1, pX1hi, pX1lo, nullptr, nag);
    mma_gemm<256, 256, false><<<dim3(4, mtilesA), 256, DSMEM>>>(
        (const __nv_bfloat16*)pX1hi, (const __nv_bfloat16*)pX1lo,
        pWh2h, pWh2l, b_h2, nullptr, nullptr, pX2, nag);
    out_k<<<(n_nodes * 32 + t - 1) / t, t>>>(W_out, b_out, nag, out);
}